// round 14
// baseline (speedup 1.0000x reference)
#include <cuda_runtime.h>
#include <cuda_bf16.h>
#include <cuda_fp16.h>
#include <cstdint>

// ---------------------------------------------------------------------------
// Problem constants
// ---------------------------------------------------------------------------
#define BDIM 2
#define TDIM 4096
#define CDIM 768
#define HDIM 12
#define DDIM 64
#define N3DIM 2304            // 3*C
#define MTOT  (BDIM*TDIM)     // 8192

// ---------------------------------------------------------------------------
// Device scratch (no allocation in kernel_launch) — pure fp16 pipeline
// ---------------------------------------------------------------------------
__device__ __align__(16) __half g_x [MTOT*CDIM];
__device__ __align__(16) __half g_y [MTOT*CDIM];
__device__ __align__(16) __half g_WaT[N3DIM*CDIM];   // [N,K]
__device__ __align__(16) __half g_WpT[CDIM*CDIM];    // [N,K]
__device__ __align__(16) __half g_q[BDIM*HDIM*TDIM*DDIM];   // x0.125
__device__ __align__(16) __half g_k[BDIM*HDIM*TDIM*DDIM];
__device__ __align__(16) __half g_v[BDIM*HDIM*TDIM*DDIM];

// ---------------------------------------------------------------------------
// Helpers (all sm_80-legal: mma.sync fp16, ldmatrix, cp.async)
// ---------------------------------------------------------------------------
__device__ __forceinline__ uint32_t smem_u32(const void* p) {
    uint32_t a;
    asm("{ .reg .u64 t; cvta.to.shared.u64 t, %1; cvt.u32.u64 %0, t; }"
        : "=r"(a) : "l"(p));
    return a;
}
#define SW128(off) ((off) ^ (((off) >> 3) & 0x70))

__device__ __forceinline__ void cp16(uint32_t dst, const void* src) {
    asm volatile("cp.async.cg.shared.global [%0], [%1], 16;"
                 :: "r"(dst), "l"(src) : "memory");
}
#define CP_COMMIT() asm volatile("cp.async.commit_group;" ::: "memory")
#define CP_WAIT0()  asm volatile("cp.async.wait_group 0;"  ::: "memory")
#define CP_WAIT1()  asm volatile("cp.async.wait_group 1;"  ::: "memory")

__device__ __forceinline__ void ldm_x4(uint32_t a, uint32_t& r0, uint32_t& r1,
                                       uint32_t& r2, uint32_t& r3) {
    asm volatile("ldmatrix.sync.aligned.m8n8.x4.shared.b16 {%0,%1,%2,%3}, [%4];"
                 : "=r"(r0), "=r"(r1), "=r"(r2), "=r"(r3) : "r"(a));
}
__device__ __forceinline__ void ldm_x4t(uint32_t a, uint32_t& r0, uint32_t& r1,
                                        uint32_t& r2, uint32_t& r3) {
    asm volatile("ldmatrix.sync.aligned.m8n8.x4.trans.shared.b16 {%0,%1,%2,%3}, [%4];"
                 : "=r"(r0), "=r"(r1), "=r"(r2), "=r"(r3) : "r"(a));
}
__device__ __forceinline__ void mma_fp16(float (&c)[4], const uint32_t (&a)[4],
                                         uint32_t b0, uint32_t b1) {
    asm volatile("mma.sync.aligned.m16n8k16.row.col.f32.f16.f16.f32 "
                 "{%0,%1,%2,%3}, {%4,%5,%6,%7}, {%8,%9}, {%0,%1,%2,%3};"
                 : "+f"(c[0]), "+f"(c[1]), "+f"(c[2]), "+f"(c[3])
                 : "r"(a[0]), "r"(a[1]), "r"(a[2]), "r"(a[3]), "r"(b0), "r"(b1));
}
// pack two halves into u32 (a -> low, b -> high)
__device__ __forceinline__ uint32_t pkh(__half a, __half b) {
    __half2 t = __halves2half2(a, b);
    return *(uint32_t*)&t;
}
__device__ __forceinline__ float ex2f(float x) {
    float y; asm("ex2.approx.ftz.f32 %0, %1;" : "=f"(y) : "f"(x)); return y;
}

// ---------------------------------------------------------------------------
// Conversion kernels
// ---------------------------------------------------------------------------
__global__ __launch_bounds__(256) void conv_f16(const float* __restrict__ in,
                                                __half* __restrict__ out, int n2) {
    int i = blockIdx.x * blockDim.x + threadIdx.x;
    if (i >= n2) return;
    float2 v = ((const float2*)in)[i];
    ((uint32_t*)out)[i] = pkh(__float2half_rn(v.x), __float2half_rn(v.y));
}

// W [K,N] fp32 -> WT [N,K] fp16 (transpose + convert). block (32,8).
__global__ __launch_bounds__(256) void wconv_T(const float* __restrict__ W,
                                               __half* __restrict__ WT,
                                               int K, int N) {
    __shared__ float tile[32][33];
    const int tx = threadIdx.x, ty = threadIdx.y;
    const int bn = blockIdx.x * 32, bk = blockIdx.y * 32;
    #pragma unroll
    for (int i = 0; i < 4; i++)
        tile[ty + 8*i][tx] = W[(size_t)(bk + ty + 8*i) * N + bn + tx];
    __syncthreads();
    #pragma unroll
    for (int i = 0; i < 4; i++)
        WT[(size_t)(bn + ty + 8*i) * K + bk + tx] = __float2half_rn(tile[tx][ty + 8*i]);
}

// ---------------------------------------------------------------------------
// Single-pass fp16 HMMA GEMM mainloop, templated warp-M (MF*16).
// 512 thr = 16 warps (4m x 4n), warp tile (MF*16)x32, CTA (MF*64)x128,
// K-chunk 64, 3-stage.  smem stage: A (MF*8KB) @0, B (16KB) @MF*8KB.
// ---------------------------------------------------------------------------
template<int MF>
__device__ __forceinline__ void gemm_issue(const __half* A, const __half* B,
                                           int am0, int bn0, int k0,
                                           uint32_t stbase, int tid) {
    #pragma unroll
    for (int i = 0; i < MF; i++) {                 // A: MF*64 rows
        int s2 = tid + (i << 9);
        int row = s2 >> 3, c16 = s2 & 7;
        cp16(stbase + SW128((uint32_t)(row*128 + (c16 << 4))),
             A + (size_t)(am0 + row) * 768 + k0 + (c16 << 3));
    }
    #pragma unroll
    for (int i = 0; i < 2; i++) {                  // B: 128 rows
        int s2 = tid + (i << 9);
        int row = s2 >> 3, c16 = s2 & 7;
        cp16(stbase + (uint32_t)(MF*8192) + SW128((uint32_t)(row*128 + (c16 << 4))),
             B + (size_t)(bn0 + row) * 768 + k0 + (c16 << 3));
    }
    CP_COMMIT();
}

template<int MF>
__device__ __forceinline__ void gemm_main(const __half* A, const __half* B,
                                          int am0, int bn0,
                                          float (&acc)[MF][4][4], char* sm) {
    const int GST = MF*8192 + 16384;
    const int tid = threadIdx.x;
    const int wid = tid >> 5, lane = tid & 31;
    const uint32_t sb = smem_u32(sm);
    const int wm0 = (wid & 3) * (MF*16);
    const int wn0 = (wid >> 2) * 32;
    const int r = lane & 7, g = lane >> 3;

    gemm_issue<MF>(A, B, am0, bn0, 0,  sb,       tid);
    gemm_issue<MF>(A, B, am0, bn0, 64, sb + GST, tid);

    for (int c = 0; c < 12; c++) {
        if (c < 11) CP_WAIT1(); else CP_WAIT0();
        __syncthreads();
        if (c < 10)
            gemm_issue<MF>(A, B, am0, bn0, (c+2)*64,
                           sb + (uint32_t)(((c+2)%3) * GST), tid);
        const uint32_t st = sb + (uint32_t)((c % 3) * GST);
        #pragma unroll
        for (int kf = 0; kf < 4; kf++) {
            const int k0 = kf * 16;
            uint32_t af[MF][4];
            #pragma unroll
            for (int mf = 0; mf < MF; mf++) {
                uint32_t off = SW128((uint32_t)(
                    (wm0 + mf*16 + ((g & 1) ? 8 : 0) + r) * 128 +
                    (k0 + ((g & 2) ? 8 : 0)) * 2));
                ldm_x4(st + off, af[mf][0], af[mf][1], af[mf][2], af[mf][3]);
            }
            uint32_t bf[4][2];
            #pragma unroll
            for (int nb = 0; nb < 2; nb++) {
                uint32_t off = SW128((uint32_t)(
                    (wn0 + nb*16 + ((g & 2) ? 8 : 0) + r) * 128 +
                    (k0 + ((g & 1) ? 8 : 0)) * 2));
                uint32_t t0, t1, t2, t3;
                ldm_x4(st + (uint32_t)(MF*8192) + off, t0, t1, t2, t3);
                bf[2*nb][0] = t0; bf[2*nb][1] = t1;
                bf[2*nb+1][0] = t2; bf[2*nb+1][1] = t3;
            }
            #pragma unroll
            for (int mf = 0; mf < MF; mf++)
                #pragma unroll
                for (int nf = 0; nf < 4; nf++)
                    mma_fp16(acc[mf][nf], af[mf], bf[nf][0], bf[nf][1]);
        }
    }
}

#define GSMEM4 (3*(4*8192 + 16384))   // qkv: 147456
#define GSMEM2 (3*(2*8192 + 16384))   // proj: 98304

// ---------------------------------------------------------------------------
// QKV GEMM: x @ W_attn + b.  q (x0.125), k, v -> fp16 [b*h][t][d].
// CTA 256x128, grid (18, 32), 512 threads
// ---------------------------------------------------------------------------
__global__ __launch_bounds__(512) void qkv_mma(const float* __restrict__ bias) {
    extern __shared__ char sm[];
    const int bm = blockIdx.y * 256;
    const int bn = blockIdx.x * 128;
    float acc[4][4][4] = {};
    gemm_main<4>(g_x, g_WaT, bm, bn, acc, sm);

    const int wid = threadIdx.x >> 5, lane = threadIdx.x & 31;
    const int which = bn / CDIM;              // 0=q 1=k 2=v (tiles never straddle)
    const int batch = bm >> 12;               // 256-row tile never straddles batch
    const float sc = (which == 0) ? 0.125f : 1.0f;
    __half* dst = which == 0 ? g_q : which == 1 ? g_k : g_v;

    #pragma unroll
    for (int nf = 0; nf < 4; nf++) {
        const int gcol = bn + (wid >> 2) * 32 + nf * 8 + (lane & 3) * 2;
        const float b0 = __ldg(bias + gcol), b1 = __ldg(bias + gcol + 1);
        const int within = gcol % CDIM;
        const int head = within >> 6, d = within & 63;
        #pragma unroll
        for (int mf = 0; mf < 4; mf++) {
            const int t = (bm & (TDIM - 1)) + (wid & 3) * 64 + mf * 16 + (lane >> 2);
            size_t o0 = ((size_t)(batch*HDIM + head)*TDIM + t)     * DDIM + d;
            size_t o1 = ((size_t)(batch*HDIM + head)*TDIM + t + 8) * DDIM + d;
            *(uint32_t*)(dst + o0) = pkh(__float2half_rn((acc[mf][nf][0]+b0)*sc),
                                         __float2half_rn((acc[mf][nf][1]+b1)*sc));
            *(uint32_t*)(dst + o1) = pkh(__float2half_rn((acc[mf][nf][2]+b0)*sc),
                                         __float2half_rn((acc[mf][nf][3]+b1)*sc));
        }
    }
}

// ---------------------------------------------------------------------------
// Projection GEMM: y @ W_proj + b -> d_out fp32.  CTA 128x128, grid (6, 64)
// ---------------------------------------------------------------------------
__global__ __launch_bounds__(512) void proj_mma(const float* __restrict__ bias,
                                                float* __restrict__ out) {
    extern __shared__ char sm[];
    const int bm = blockIdx.y * 128;
    const int bn = blockIdx.x * 128;
    float acc[2][4][4] = {};
    gemm_main<2>(g_y, g_WpT, bm, bn, acc, sm);

    const int wid = threadIdx.x >> 5, lane = threadIdx.x & 31;
    #pragma unroll
    for (int nf = 0; nf < 4; nf++) {
        const int gcol = bn + (wid >> 2) * 32 + nf * 8 + (lane & 3) * 2;
        const float b0 = __ldg(bias + gcol), b1 = __ldg(bias + gcol + 1);
        #pragma unroll
        for (int mf = 0; mf < 2; mf++) {
            const int m = bm + (wid & 3) * 32 + mf * 16 + (lane >> 2);
            *(float2*)(out + (size_t)m * CDIM + gcol) =
                make_float2(acc[mf][nf][0] + b0, acc[mf][nf][1] + b1);
            *(float2*)(out + (size_t)(m + 8) * CDIM + gcol) =
                make_float2(acc[mf][nf][2] + b0, acc[mf][nf][3] + b1);
        }
    }
}

// ---------------------------------------------------------------------------
// Flash attention, pure fp16 single-pass HMMA, 128-wide K/V tiles,
// ping-pong S registers (R13) + L-VIA-MMA: softmax row-sums computed by
// 8 HMMAs against a constant all-ones B fragment (0x3C003C00) — removes the
// 32 FADDs + 4 shuffle reductions per thread per tile from the scalar chain.
// grid (32 q-tiles, 24 bh), 256 thr, 1 CTA/SM.  Q fp16 in registers;
// K,V fp16 in smem (stage 32KB: K@0 (128 rows) V@16K), 3-stage cp.async.
// ---------------------------------------------------------------------------
#define FSMEM (3*32768)
#define ONES_B 0x3C003C00u

__global__ __launch_bounds__(256) void flash_mma() {
    extern __shared__ char sm[];
    const uint32_t sb = smem_u32(sm);
    const int tid = threadIdx.x, wid = tid >> 5, lane = tid & 31;
    const int qt = (int)gridDim.x - 1 - (int)blockIdx.x;   // heavy tiles first
    const int bh = blockIdx.y;
    const int qbase = qt * 128;
    const int ntiles = qt + 1;                              // 128-wide K tiles

    const __half* qp = g_q + (size_t)bh * TDIM * DDIM;
    const __half* kp = g_k + (size_t)bh * TDIM * DDIM;
    const __half* vp = g_v + (size_t)bh * TDIM * DDIM;

    // Q fragments, register resident
    uint32_t qf[4][4];
    {
        const int row = qbase + wid * 16 + (lane >> 2);
        const int colb = (lane & 3) * 2;
        #pragma unroll
        for (int kf = 0; kf < 4; kf++)
            #pragma unroll
            for (int a = 0; a < 4; a++) {
                int rr = row + ((a & 1) ? 8 : 0);
                int cc = kf * 16 + colb + ((a & 2) ? 8 : 0);
                qf[kf][a] = *(const uint32_t*)(qp + (size_t)rr * DDIM + cc);
            }
    }

    float m0 = -1e30f, m1 = -1e30f, l0 = 0.f, l1 = 0.f;
    float o[8][4] = {};
    const int r = lane & 7, g = lane >> 3;
    const float LOG2E = 1.4426950408889634f;

    // K/V tile loader (cp.async, 8 x 16B per thread; stage = 32KB)
    auto issue = [&](int jt) {
        const int kb = jt * 128;
        const uint32_t stg = sb + (uint32_t)((jt % 3) << 15);
        #pragma unroll
        for (int arr = 0; arr < 2; arr++) {
            const __half* base = arr == 0 ? kp : vp;
            #pragma unroll
            for (int i = 0; i < 4; i++) {
                int s2 = tid + (i << 8);            // 0..1023 (128 rows x 8)
                int row = s2 >> 3, c16 = s2 & 7;
                cp16(stg + (arr << 14) + SW128((uint32_t)(row*128 + (c16 << 4))),
                     base + (size_t)(kb + row) * DDIM + (c16 << 3));
            }
        }
        CP_COMMIT();
    };

    // S accumulation from K stage into the given register array
    auto computeS = [&](uint32_t st, float (&s)[16][4]) {
        #pragma unroll
        for (int nf = 0; nf < 16; nf++)
            #pragma unroll
            for (int q = 0; q < 4; q++) s[nf][q] = 0.f;
        #pragma unroll
        for (int kf = 0; kf < 4; kf++) {
            const int k0 = kf * 16;
            #pragma unroll
            for (int nb = 0; nb < 8; nb++) {
                uint32_t off = SW128((uint32_t)(
                    (nb*16 + ((g & 2) ? 8 : 0) + r) * 128 +
                    (k0 + ((g & 1) ? 8 : 0)) * 2));
                uint32_t h0, h1, h2, h3;
                ldm_x4(st + off, h0, h1, h2, h3);          // K
                mma_fp16(s[2*nb],   qf[kf], h0, h1);
                mma_fp16(s[2*nb+1], qf[kf], h2, h3);
            }
        }
    };

    float sA[16][4], sB[16][4];

    // Per-tile body: softmax+PV on scur while S(jt+1) accumulates into snx.
    auto body = [&](int jt, float (&scur)[16][4], float (&snx)[16][4]) {
        CP_WAIT0();              // tile jt+1 (if issued) fully arrived
        __syncthreads();         // visible CTA-wide; stage jt-1 free
        if (jt + 2 < ntiles) issue(jt + 2);
        const int kb = jt * 128;
        const uint32_t st = sb + (uint32_t)((jt % 3) << 15);

        // ---- S(jt+1) FIRST: fills the tensor pipe under the softmax below ----
        if (jt + 1 < ntiles)
            computeS(sb + (uint32_t)(((jt + 1) % 3) << 15), snx);

        // ---- causal mask (diagonal tile only) ----
        const int row0 = qbase + wid * 16 + (lane >> 2);
        if (kb + 127 > row0) {
            #pragma unroll
            for (int nf = 0; nf < 16; nf++) {
                int col = kb + nf * 8 + (lane & 3) * 2;
                if (col     > row0)     scur[nf][0] = -1e30f;
                if (col + 1 > row0)     scur[nf][1] = -1e30f;
                if (col     > row0 + 8) scur[nf][2] = -1e30f;
                if (col + 1 > row0 + 8) scur[nf][3] = -1e30f;
            }
        }

        // ---- online softmax (max via shuffles; sums via MMA below) ----
        float rmax0 = -1e30f, rmax1 = -1e30f;
        #pragma unroll
        for (int nf = 0; nf < 16; nf++) {
            rmax0 = fmaxf(rmax0, fmaxf(scur[nf][0], scur[nf][1]));
            rmax1 = fmaxf(rmax1, fmaxf(scur[nf][2], scur[nf][3]));
        }
        rmax0 = fmaxf(rmax0, __shfl_xor_sync(0xffffffffu, rmax0, 1));
        rmax0 = fmaxf(rmax0, __shfl_xor_sync(0xffffffffu, rmax0, 2));
        rmax1 = fmaxf(rmax1, __shfl_xor_sync(0xffffffffu, rmax1, 1));
        rmax1 = fmaxf(rmax1, __shfl_xor_sync(0xffffffffu, rmax1, 2));
        const float mn0 = fmaxf(m0, rmax0), mn1 = fmaxf(m1, rmax1);
        const float a0 = ex2f((m0 - mn0) * LOG2E);
        const float a1 = ex2f((m1 - mn1) * LOG2E);
        m0 = mn0; m1 = mn1;
        const float ml0 = mn0 * LOG2E, ml1 = mn1 * LOG2E;
        #pragma unroll
        for (int nf = 0; nf < 16; nf++) {
            scur[nf][0] = ex2f(fmaf(scur[nf][0], LOG2E, -ml0));
            scur[nf][1] = ex2f(fmaf(scur[nf][1], LOG2E, -ml0));
            scur[nf][2] = ex2f(fmaf(scur[nf][2], LOG2E, -ml1));
            scur[nf][3] = ex2f(fmaf(scur[nf][3], LOG2E, -ml1));
        }
        #pragma unroll
        for (int nf = 0; nf < 8; nf++) {
            o[nf][0] *= a0; o[nf][1] *= a0;
            o[nf][2] *= a1; o[nf][3] *= a1;
        }

        // ---- P -> fp16 A-fragments ----
        uint32_t pf[8][4];
        #pragma unroll
        for (int j = 0; j < 8; j++) {
            #pragma unroll
            for (int half = 0; half < 2; half++) {
                pf[j][2*half]     = pkh(__float2half_rn(scur[2*j + half][0]),
                                        __float2half_rn(scur[2*j + half][1]));
                pf[j][2*half + 1] = pkh(__float2half_rn(scur[2*j + half][2]),
                                        __float2half_rn(scur[2*j + half][3]));
            }
        }

        // ---- row sums l via MMA against constant all-ones B fragment ----
        float la[4] = {0.f, 0.f, 0.f, 0.f};
        #pragma unroll
        for (int j = 0; j < 8; j++)
            mma_fp16(la, pf[j], ONES_B, ONES_B);
        l0 = l0 * a0 + la[0];
        l1 = l1 * a1 + la[2];

        // ---- O += P.V (tile jt), V^T via ldmatrix.trans ----
        #pragma unroll
        for (int j = 0; j < 8; j++) {
            #pragma unroll
            for (int nb = 0; nb < 4; nb++) {
                uint32_t off = SW128((uint32_t)(
                    (j*16 + ((g & 1) ? 8 : 0) + r) * 128 +
                    (nb*16 + ((g & 2) ? 8 : 0)) * 2));
                uint32_t h0, h1, h2, h3;
                ldm_x4t(st + 16384 + off, h0, h1, h2, h3);   // V
                mma_fp16(o[2*nb],   pf[j], h0, h1);
                mma_fp16(o[2*nb+1], pf[j], h2, h3);
            }
        }
    };

    // Prologue: load tiles 0 (and 1), compute S(0) into sA
    issue(0);
    if (ntiles > 1) { issue(1); CP_WAIT1(); } else { CP_WAIT0(); }
    __syncthreads();
    computeS(sb, sA);

    for (int jt = 0; jt < ntiles; jt++) {
        if (jt & 1) body(jt, sB, sA);
        else        body(jt, sA, sB);
    }

    // ---- epilogue: o / l -> fp16 into g_y ----
    const float inv0 = 1.0f / l0, inv1 = 1.0f / l1;
    const int batch = bh / HDIM, hh = bh % HDIM;
    const int row = qbase + wid * 16 + (lane >> 2);
    const size_t rb0 = ((size_t)(batch * TDIM + row))     * CDIM + hh * DDIM;
    const size_t rb1 = ((size_t)(batch * TDIM + row + 8)) * CDIM + hh * DDIM;
    #pragma unroll
    for (int nf = 0; nf < 8; nf++) {
        const int d = nf * 8 + (lane & 3) * 2;
        *(uint32_t*)(g_y + rb0 + d) = pkh(__float2half_rn(o[nf][0] * inv0),
                                          __float2half_rn(o[nf][1] * inv0));
        *(uint32_t*)(g_y + rb1 + d) = pkh(__float2half_rn(o[nf][2] * inv1),
                                          __float2half_rn(o[nf][3] * inv1));
    }
}

// ---------------------------------------------------------------------------
extern "C" void kernel_launch(void* const* d_in, const int* in_sizes, int n_in,
                              void* d_out, int out_size) {
    const float *x = nullptr, *Wa = nullptr, *ba = nullptr, *Wp = nullptr, *bp = nullptr;
    for (int i = 0; i < n_in; i++) {
        switch (in_sizes[i]) {
            case 6291456: x  = (const float*)d_in[i]; break;   // [2,4096,768]
            case 1769472: Wa = (const float*)d_in[i]; break;   // [768,2304]
            case 2304:    ba = (const float*)d_in[i]; break;
            case 589824:  Wp = (const float*)d_in[i]; break;   // [768,768]
            case 768:     bp = (const float*)d_in[i]; break;
        }
    }

    cudaFuncSetAttribute(qkv_mma,   cudaFuncAttributeMaxDynamicSharedMemorySize, GSMEM4);
    cudaFuncSetAttribute(proj_mma,  cudaFuncAttributeMaxDynamicSharedMemorySize, GSMEM2);
    cudaFuncSetAttribute(flash_mma, cudaFuncAttributeMaxDynamicSharedMemorySize, FSMEM);

    __half *xd, *wat, *wpt;
    cudaGetSymbolAddress((void**)&xd,  g_x);
    cudaGetSymbolAddress((void**)&wat, g_WaT);
    cudaGetSymbolAddress((void**)&wpt, g_WpT);

    conv_f16<<<(MTOT*CDIM/2 + 255)/256, 256>>>(x, xd, MTOT*CDIM/2);
    wconv_T<<<dim3(N3DIM/32, CDIM/32), dim3(32, 8)>>>(Wa, wat, CDIM, N3DIM);
    wconv_T<<<dim3(CDIM/32,  CDIM/32), dim3(32, 8)>>>(Wp, wpt, CDIM, CDIM);
    qkv_mma<<<dim3(N3DIM/128, MTOT/256), 512, GSMEM4>>>(ba);       // (18,32)
    flash_mma<<<dim3(TDIM/128, BDIM*HDIM), 256, FSMEM>>>();        // (32,24)
    proj_mma<<<dim3(CDIM/128, MTOT/128), 512, GSMEM2>>>(bp, (float*)d_out); // (6,64)
}

// round 15
// speedup vs baseline: 1.0380x; 1.0380x over previous
#include <cuda_runtime.h>
#include <cuda_bf16.h>
#include <cuda_fp16.h>
#include <cstdint>

// ---------------------------------------------------------------------------
// Problem constants
// ---------------------------------------------------------------------------
#define BDIM 2
#define TDIM 4096
#define CDIM 768
#define HDIM 12
#define DDIM 64
#define N3DIM 2304            // 3*C
#define MTOT  (BDIM*TDIM)     // 8192

// ---------------------------------------------------------------------------
// Device scratch (no allocation in kernel_launch) — pure fp16 pipeline
// ---------------------------------------------------------------------------
__device__ __align__(16) __half g_x [MTOT*CDIM];
__device__ __align__(16) __half g_y [MTOT*CDIM];
__device__ __align__(16) __half g_WaT[N3DIM*CDIM];   // [N,K]
__device__ __align__(16) __half g_WpT[CDIM*CDIM];    // [N,K]
__device__ __align__(16) __half g_q[BDIM*HDIM*TDIM*DDIM];   // x0.125
__device__ __align__(16) __half g_k[BDIM*HDIM*TDIM*DDIM];
__device__ __align__(16) __half g_v[BDIM*HDIM*TDIM*DDIM];

// ---------------------------------------------------------------------------
// Helpers (all sm_80-legal: mma.sync fp16, ldmatrix, cp.async)
// ---------------------------------------------------------------------------
__device__ __forceinline__ uint32_t smem_u32(const void* p) {
    uint32_t a;
    asm("{ .reg .u64 t; cvta.to.shared.u64 t, %1; cvt.u32.u64 %0, t; }"
        : "=r"(a) : "l"(p));
    return a;
}
#define SW128(off) ((off) ^ (((off) >> 3) & 0x70))

__device__ __forceinline__ void cp16(uint32_t dst, const void* src) {
    asm volatile("cp.async.cg.shared.global [%0], [%1], 16;"
                 :: "r"(dst), "l"(src) : "memory");
}
#define CP_COMMIT() asm volatile("cp.async.commit_group;" ::: "memory")
#define CP_WAIT0()  asm volatile("cp.async.wait_group 0;"  ::: "memory")
#define CP_WAIT1()  asm volatile("cp.async.wait_group 1;"  ::: "memory")

__device__ __forceinline__ void ldm_x4(uint32_t a, uint32_t& r0, uint32_t& r1,
                                       uint32_t& r2, uint32_t& r3) {
    asm volatile("ldmatrix.sync.aligned.m8n8.x4.shared.b16 {%0,%1,%2,%3}, [%4];"
                 : "=r"(r0), "=r"(r1), "=r"(r2), "=r"(r3) : "r"(a));
}
__device__ __forceinline__ void ldm_x4t(uint32_t a, uint32_t& r0, uint32_t& r1,
                                        uint32_t& r2, uint32_t& r3) {
    asm volatile("ldmatrix.sync.aligned.m8n8.x4.trans.shared.b16 {%0,%1,%2,%3}, [%4];"
                 : "=r"(r0), "=r"(r1), "=r"(r2), "=r"(r3) : "r"(a));
}
__device__ __forceinline__ void mma_fp16(float (&c)[4], const uint32_t (&a)[4],
                                         uint32_t b0, uint32_t b1) {
    asm volatile("mma.sync.aligned.m16n8k16.row.col.f32.f16.f16.f32 "
                 "{%0,%1,%2,%3}, {%4,%5,%6,%7}, {%8,%9}, {%0,%1,%2,%3};"
                 : "+f"(c[0]), "+f"(c[1]), "+f"(c[2]), "+f"(c[3])
                 : "r"(a[0]), "r"(a[1]), "r"(a[2]), "r"(a[3]), "r"(b0), "r"(b1));
}
// pack two halves into u32 (a -> low, b -> high)
__device__ __forceinline__ uint32_t pkh(__half a, __half b) {
    __half2 t = __halves2half2(a, b);
    return *(uint32_t*)&t;
}
__device__ __forceinline__ float ex2f(float x) {
    float y; asm("ex2.approx.ftz.f32 %0, %1;" : "=f"(y) : "f"(x)); return y;
}

// ---------------------------------------------------------------------------
// Conversion kernels
// ---------------------------------------------------------------------------
__global__ __launch_bounds__(256) void conv_f16(const float* __restrict__ in,
                                                __half* __restrict__ out, int n2) {
    int i = blockIdx.x * blockDim.x + threadIdx.x;
    if (i >= n2) return;
    float2 v = ((const float2*)in)[i];
    ((uint32_t*)out)[i] = pkh(__float2half_rn(v.x), __float2half_rn(v.y));
}

// W [K,N] fp32 -> WT [N,K] fp16 (transpose + convert). block (32,8).
__global__ __launch_bounds__(256) void wconv_T(const float* __restrict__ W,
                                               __half* __restrict__ WT,
                                               int K, int N) {
    __shared__ float tile[32][33];
    const int tx = threadIdx.x, ty = threadIdx.y;
    const int bn = blockIdx.x * 32, bk = blockIdx.y * 32;
    #pragma unroll
    for (int i = 0; i < 4; i++)
        tile[ty + 8*i][tx] = W[(size_t)(bk + ty + 8*i) * N + bn + tx];
    __syncthreads();
    #pragma unroll
    for (int i = 0; i < 4; i++)
        WT[(size_t)(bn + ty + 8*i) * K + bk + tx] = __float2half_rn(tile[tx][ty + 8*i]);
}

// ---------------------------------------------------------------------------
// Single-pass fp16 HMMA GEMM mainloop, templated warp-M (MF*16).
// 512 thr = 16 warps (4m x 4n), warp tile (MF*16)x32, CTA (MF*64)x128,
// K-chunk 64, 3-stage.  smem stage: A (MF*8KB) @0, B (16KB) @MF*8KB.
// ---------------------------------------------------------------------------
template<int MF>
__device__ __forceinline__ void gemm_issue(const __half* A, const __half* B,
                                           int am0, int bn0, int k0,
                                           uint32_t stbase, int tid) {
    #pragma unroll
    for (int i = 0; i < MF; i++) {                 // A: MF*64 rows
        int s2 = tid + (i << 9);
        int row = s2 >> 3, c16 = s2 & 7;
        cp16(stbase + SW128((uint32_t)(row*128 + (c16 << 4))),
             A + (size_t)(am0 + row) * 768 + k0 + (c16 << 3));
    }
    #pragma unroll
    for (int i = 0; i < 2; i++) {                  // B: 128 rows
        int s2 = tid + (i << 9);
        int row = s2 >> 3, c16 = s2 & 7;
        cp16(stbase + (uint32_t)(MF*8192) + SW128((uint32_t)(row*128 + (c16 << 4))),
             B + (size_t)(bn0 + row) * 768 + k0 + (c16 << 3));
    }
    CP_COMMIT();
}

template<int MF>
__device__ __forceinline__ void gemm_main(const __half* A, const __half* B,
                                          int am0, int bn0,
                                          float (&acc)[MF][4][4], char* sm) {
    const int GST = MF*8192 + 16384;
    const int tid = threadIdx.x;
    const int wid = tid >> 5, lane = tid & 31;
    const uint32_t sb = smem_u32(sm);
    const int wm0 = (wid & 3) * (MF*16);
    const int wn0 = (wid >> 2) * 32;
    const int r = lane & 7, g = lane >> 3;

    gemm_issue<MF>(A, B, am0, bn0, 0,  sb,       tid);
    gemm_issue<MF>(A, B, am0, bn0, 64, sb + GST, tid);

    for (int c = 0; c < 12; c++) {
        if (c < 11) CP_WAIT1(); else CP_WAIT0();
        __syncthreads();
        if (c < 10)
            gemm_issue<MF>(A, B, am0, bn0, (c+2)*64,
                           sb + (uint32_t)(((c+2)%3) * GST), tid);
        const uint32_t st = sb + (uint32_t)((c % 3) * GST);
        #pragma unroll
        for (int kf = 0; kf < 4; kf++) {
            const int k0 = kf * 16;
            uint32_t af[MF][4];
            #pragma unroll
            for (int mf = 0; mf < MF; mf++) {
                uint32_t off = SW128((uint32_t)(
                    (wm0 + mf*16 + ((g & 1) ? 8 : 0) + r) * 128 +
                    (k0 + ((g & 2) ? 8 : 0)) * 2));
                ldm_x4(st + off, af[mf][0], af[mf][1], af[mf][2], af[mf][3]);
            }
            uint32_t bf[4][2];
            #pragma unroll
            for (int nb = 0; nb < 2; nb++) {
                uint32_t off = SW128((uint32_t)(
                    (wn0 + nb*16 + ((g & 2) ? 8 : 0) + r) * 128 +
                    (k0 + ((g & 1) ? 8 : 0)) * 2));
                uint32_t t0, t1, t2, t3;
                ldm_x4(st + (uint32_t)(MF*8192) + off, t0, t1, t2, t3);
                bf[2*nb][0] = t0; bf[2*nb][1] = t1;
                bf[2*nb+1][0] = t2; bf[2*nb+1][1] = t3;
            }
            #pragma unroll
            for (int mf = 0; mf < MF; mf++)
                #pragma unroll
                for (int nf = 0; nf < 4; nf++)
                    mma_fp16(acc[mf][nf], af[mf], bf[nf][0], bf[nf][1]);
        }
    }
}

#define GSMEM4 (3*(4*8192 + 16384))   // qkv: 147456
#define GSMEM2 (3*(2*8192 + 16384))   // proj: 98304

// ---------------------------------------------------------------------------
// QKV GEMM: x @ W_attn + b.  q (x0.125), k, v -> fp16 [b*h][t][d].
// CTA 256x128, grid (18, 32), 512 threads
// ---------------------------------------------------------------------------
__global__ __launch_bounds__(512) void qkv_mma(const float* __restrict__ bias) {
    extern __shared__ char sm[];
    const int bm = blockIdx.y * 256;
    const int bn = blockIdx.x * 128;
    float acc[4][4][4] = {};
    gemm_main<4>(g_x, g_WaT, bm, bn, acc, sm);

    const int wid = threadIdx.x >> 5, lane = threadIdx.x & 31;
    const int which = bn / CDIM;              // 0=q 1=k 2=v (tiles never straddle)
    const int batch = bm >> 12;               // 256-row tile never straddles batch
    const float sc = (which == 0) ? 0.125f : 1.0f;
    __half* dst = which == 0 ? g_q : which == 1 ? g_k : g_v;

    #pragma unroll
    for (int nf = 0; nf < 4; nf++) {
        const int gcol = bn + (wid >> 2) * 32 + nf * 8 + (lane & 3) * 2;
        const float b0 = __ldg(bias + gcol), b1 = __ldg(bias + gcol + 1);
        const int within = gcol % CDIM;
        const int head = within >> 6, d = within & 63;
        #pragma unroll
        for (int mf = 0; mf < 4; mf++) {
            const int t = (bm & (TDIM - 1)) + (wid & 3) * 64 + mf * 16 + (lane >> 2);
            size_t o0 = ((size_t)(batch*HDIM + head)*TDIM + t)     * DDIM + d;
            size_t o1 = ((size_t)(batch*HDIM + head)*TDIM + t + 8) * DDIM + d;
            *(uint32_t*)(dst + o0) = pkh(__float2half_rn((acc[mf][nf][0]+b0)*sc),
                                         __float2half_rn((acc[mf][nf][1]+b1)*sc));
            *(uint32_t*)(dst + o1) = pkh(__float2half_rn((acc[mf][nf][2]+b0)*sc),
                                         __float2half_rn((acc[mf][nf][3]+b1)*sc));
        }
    }
}

// ---------------------------------------------------------------------------
// Projection GEMM: y @ W_proj + b -> d_out fp32.  CTA 128x128, grid (6, 64)
// ---------------------------------------------------------------------------
__global__ __launch_bounds__(512) void proj_mma(const float* __restrict__ bias,
                                                float* __restrict__ out) {
    extern __shared__ char sm[];
    const int bm = blockIdx.y * 128;
    const int bn = blockIdx.x * 128;
    float acc[2][4][4] = {};
    gemm_main<2>(g_y, g_WpT, bm, bn, acc, sm);

    const int wid = threadIdx.x >> 5, lane = threadIdx.x & 31;
    #pragma unroll
    for (int nf = 0; nf < 4; nf++) {
        const int gcol = bn + (wid >> 2) * 32 + nf * 8 + (lane & 3) * 2;
        const float b0 = __ldg(bias + gcol), b1 = __ldg(bias + gcol + 1);
        #pragma unroll
        for (int mf = 0; mf < 2; mf++) {
            const int m = bm + (wid & 3) * 32 + mf * 16 + (lane >> 2);
            *(float2*)(out + (size_t)m * CDIM + gcol) =
                make_float2(acc[mf][nf][0] + b0, acc[mf][nf][1] + b1);
            *(float2*)(out + (size_t)(m + 8) * CDIM + gcol) =
                make_float2(acc[mf][nf][2] + b0, acc[mf][nf][3] + b1);
        }
    }
}

// ---------------------------------------------------------------------------
// Flash attention (R13 structure: ping-pong S registers) + TREE-REDUCED
// softmax: rmax and row-sum computed with binary trees (depth 128->20 cyc on
// the FADD chain, 64->16 on the fmax chain).  Scalar reductions stay off the
// tensor pipe (R14's l-via-MMA regressed — reverted).
// grid (32 q-tiles, 24 bh), 256 thr, 1 CTA/SM.  Q fp16 in registers;
// K,V fp16 in smem (stage 32KB: K@0 (128 rows) V@16K), 3-stage cp.async.
// ---------------------------------------------------------------------------
#define FSMEM (3*32768)

__global__ __launch_bounds__(256) void flash_mma() {
    extern __shared__ char sm[];
    const uint32_t sb = smem_u32(sm);
    const int tid = threadIdx.x, wid = tid >> 5, lane = tid & 31;
    const int qt = (int)gridDim.x - 1 - (int)blockIdx.x;   // heavy tiles first
    const int bh = blockIdx.y;
    const int qbase = qt * 128;
    const int ntiles = qt + 1;                              // 128-wide K tiles

    const __half* qp = g_q + (size_t)bh * TDIM * DDIM;
    const __half* kp = g_k + (size_t)bh * TDIM * DDIM;
    const __half* vp = g_v + (size_t)bh * TDIM * DDIM;

    // Q fragments, register resident
    uint32_t qf[4][4];
    {
        const int row = qbase + wid * 16 + (lane >> 2);
        const int colb = (lane & 3) * 2;
        #pragma unroll
        for (int kf = 0; kf < 4; kf++)
            #pragma unroll
            for (int a = 0; a < 4; a++) {
                int rr = row + ((a & 1) ? 8 : 0);
                int cc = kf * 16 + colb + ((a & 2) ? 8 : 0);
                qf[kf][a] = *(const uint32_t*)(qp + (size_t)rr * DDIM + cc);
            }
    }

    float m0 = -1e30f, m1 = -1e30f, l0 = 0.f, l1 = 0.f;
    float o[8][4] = {};
    const int r = lane & 7, g = lane >> 3;
    const float LOG2E = 1.4426950408889634f;

    // K/V tile loader (cp.async, 8 x 16B per thread; stage = 32KB)
    auto issue = [&](int jt) {
        const int kb = jt * 128;
        const uint32_t stg = sb + (uint32_t)((jt % 3) << 15);
        #pragma unroll
        for (int arr = 0; arr < 2; arr++) {
            const __half* base = arr == 0 ? kp : vp;
            #pragma unroll
            for (int i = 0; i < 4; i++) {
                int s2 = tid + (i << 8);            // 0..1023 (128 rows x 8)
                int row = s2 >> 3, c16 = s2 & 7;
                cp16(stg + (arr << 14) + SW128((uint32_t)(row*128 + (c16 << 4))),
                     base + (size_t)(kb + row) * DDIM + (c16 << 3));
            }
        }
        CP_COMMIT();
    };

    // S accumulation from K stage into the given register array
    auto computeS = [&](uint32_t st, float (&s)[16][4]) {
        #pragma unroll
        for (int nf = 0; nf < 16; nf++)
            #pragma unroll
            for (int q = 0; q < 4; q++) s[nf][q] = 0.f;
        #pragma unroll
        for (int kf = 0; kf < 4; kf++) {
            const int k0 = kf * 16;
            #pragma unroll
            for (int nb = 0; nb < 8; nb++) {
                uint32_t off = SW128((uint32_t)(
                    (nb*16 + ((g & 2) ? 8 : 0) + r) * 128 +
                    (k0 + ((g & 1) ? 8 : 0)) * 2));
                uint32_t h0, h1, h2, h3;
                ldm_x4(st + off, h0, h1, h2, h3);          // K
                mma_fp16(s[2*nb],   qf[kf], h0, h1);
                mma_fp16(s[2*nb+1], qf[kf], h2, h3);
            }
        }
    };

    float sA[16][4], sB[16][4];

    // Per-tile body: softmax+PV on scur while S(jt+1) accumulates into snx.
    auto body = [&](int jt, float (&scur)[16][4], float (&snx)[16][4]) {
        CP_WAIT0();              // tile jt+1 (if issued) fully arrived
        __syncthreads();         // visible CTA-wide; stage jt-1 free
        if (jt + 2 < ntiles) issue(jt + 2);
        const int kb = jt * 128;
        const uint32_t st = sb + (uint32_t)((jt % 3) << 15);

        // ---- S(jt+1) FIRST: fills the tensor pipe under the softmax below ----
        if (jt + 1 < ntiles)
            computeS(sb + (uint32_t)(((jt + 1) % 3) << 15), snx);

        // ---- causal mask (diagonal tile only) ----
        const int row0 = qbase + wid * 16 + (lane >> 2);
        if (kb + 127 > row0) {
            #pragma unroll
            for (int nf = 0; nf < 16; nf++) {
                int col = kb + nf * 8 + (lane & 3) * 2;
                if (col     > row0)     scur[nf][0] = -1e30f;
                if (col + 1 > row0)     scur[nf][1] = -1e30f;
                if (col     > row0 + 8) scur[nf][2] = -1e30f;
                if (col + 1 > row0 + 8) scur[nf][3] = -1e30f;
            }
        }

        // ---- row max: binary tree (depth 4 + 2 shuffles) ----
        float t0[8], t1[8];
        #pragma unroll
        for (int i = 0; i < 8; i++) {
            t0[i] = fmaxf(fmaxf(scur[2*i][0],   scur[2*i][1]),
                          fmaxf(scur[2*i+1][0], scur[2*i+1][1]));
            t1[i] = fmaxf(fmaxf(scur[2*i][2],   scur[2*i][3]),
                          fmaxf(scur[2*i+1][2], scur[2*i+1][3]));
        }
        #pragma unroll
        for (int i = 0; i < 4; i++) { t0[i] = fmaxf(t0[i], t0[i+4]); t1[i] = fmaxf(t1[i], t1[i+4]); }
        t0[0] = fmaxf(fmaxf(t0[0], t0[1]), fmaxf(t0[2], t0[3]));
        t1[0] = fmaxf(fmaxf(t1[0], t1[1]), fmaxf(t1[2], t1[3]));
        float rmax0 = t0[0], rmax1 = t1[0];
        rmax0 = fmaxf(rmax0, __shfl_xor_sync(0xffffffffu, rmax0, 1));
        rmax0 = fmaxf(rmax0, __shfl_xor_sync(0xffffffffu, rmax0, 2));
        rmax1 = fmaxf(rmax1, __shfl_xor_sync(0xffffffffu, rmax1, 1));
        rmax1 = fmaxf(rmax1, __shfl_xor_sync(0xffffffffu, rmax1, 2));
        const float mn0 = fmaxf(m0, rmax0), mn1 = fmaxf(m1, rmax1);
        const float a0 = ex2f((m0 - mn0) * LOG2E);
        const float a1 = ex2f((m1 - mn1) * LOG2E);
        m0 = mn0; m1 = mn1;
        const float ml0 = mn0 * LOG2E, ml1 = mn1 * LOG2E;

        // ---- exp (independent MUFU, overlaps in-flight S HMMAs) ----
        #pragma unroll
        for (int nf = 0; nf < 16; nf++) {
            scur[nf][0] = ex2f(fmaf(scur[nf][0], LOG2E, -ml0));
            scur[nf][1] = ex2f(fmaf(scur[nf][1], LOG2E, -ml0));
            scur[nf][2] = ex2f(fmaf(scur[nf][2], LOG2E, -ml1));
            scur[nf][3] = ex2f(fmaf(scur[nf][3], LOG2E, -ml1));
        }

        // ---- row sum: binary tree (31 adds, depth 5) + 2 shuffles ----
        #pragma unroll
        for (int i = 0; i < 8; i++) {
            t0[i] = (scur[2*i][0]   + scur[2*i][1])
                  + (scur[2*i+1][0] + scur[2*i+1][1]);
            t1[i] = (scur[2*i][2]   + scur[2*i][3])
                  + (scur[2*i+1][2] + scur[2*i+1][3]);
        }
        #pragma unroll
        for (int i = 0; i < 4; i++) { t0[i] += t0[i+4]; t1[i] += t1[i+4]; }
        float rs0 = (t0[0] + t0[1]) + (t0[2] + t0[3]);
        float rs1 = (t1[0] + t1[1]) + (t1[2] + t1[3]);
        rs0 += __shfl_xor_sync(0xffffffffu, rs0, 1);
        rs0 += __shfl_xor_sync(0xffffffffu, rs0, 2);
        rs1 += __shfl_xor_sync(0xffffffffu, rs1, 1);
        rs1 += __shfl_xor_sync(0xffffffffu, rs1, 2);
        l0 = l0 * a0 + rs0;
        l1 = l1 * a1 + rs1;
        #pragma unroll
        for (int nf = 0; nf < 8; nf++) {
            o[nf][0] *= a0; o[nf][1] *= a0;
            o[nf][2] *= a1; o[nf][3] *= a1;
        }

        // ---- P -> fp16 A-fragments ----
        uint32_t pf[8][4];
        #pragma unroll
        for (int j = 0; j < 8; j++) {
            #pragma unroll
            for (int half = 0; half < 2; half++) {
                pf[j][2*half]     = pkh(__float2half_rn(scur[2*j + half][0]),
                                        __float2half_rn(scur[2*j + half][1]));
                pf[j][2*half + 1] = pkh(__float2half_rn(scur[2*j + half][2]),
                                        __float2half_rn(scur[2*j + half][3]));
            }
        }

        // ---- O += P.V (tile jt), V^T via ldmatrix.trans ----
        #pragma unroll
        for (int j = 0; j < 8; j++) {
            #pragma unroll
            for (int nb = 0; nb < 4; nb++) {
                uint32_t off = SW128((uint32_t)(
                    (j*16 + ((g & 1) ? 8 : 0) + r) * 128 +
                    (nb*16 + ((g & 2) ? 8 : 0)) * 2));
                uint32_t h0, h1, h2, h3;
                ldm_x4t(st + 16384 + off, h0, h1, h2, h3);   // V
                mma_fp16(o[2*nb],   pf[j], h0, h1);
                mma_fp16(o[2*nb+1], pf[j], h2, h3);
            }
        }
    };

    // Prologue: load tiles 0 (and 1), compute S(0) into sA
    issue(0);
    if (ntiles > 1) { issue(1); CP_WAIT1(); } else { CP_WAIT0(); }
    __syncthreads();
    computeS(sb, sA);

    for (int jt = 0; jt < ntiles; jt++) {
        if (jt & 1) body(jt, sB, sA);
        else        body(jt, sA, sB);
    }

    // ---- epilogue: o / l -> fp16 into g_y ----
    const float inv0 = 1.0f / l0, inv1 = 1.0f / l1;
    const int batch = bh / HDIM, hh = bh % HDIM;
    const int row = qbase + wid * 16 + (lane >> 2);
    const size_t rb0 = ((size_t)(batch * TDIM + row))     * CDIM + hh * DDIM;
    const size_t rb1 = ((size_t)(batch * TDIM + row + 8)) * CDIM + hh * DDIM;
    #pragma unroll
    for (int nf = 0; nf < 8; nf++) {
        const int d = nf * 8 + (lane & 3) * 2;
        *(uint32_t*)(g_y + rb0 + d) = pkh(__float2half_rn(o[nf][0] * inv0),
                                          __float2half_rn(o[nf][1] * inv0));
        *(uint32_t*)(g_y + rb1 + d) = pkh(__float2half_rn(o[nf][2] * inv1),
                                          __float2half_rn(o[nf][3] * inv1));
    }
}

// ---------------------------------------------------------------------------
extern "C" void kernel_launch(void* const* d_in, const int* in_sizes, int n_in,
                              void* d_out, int out_size) {
    const float *x = nullptr, *Wa = nullptr, *ba = nullptr, *Wp = nullptr, *bp = nullptr;
    for (int i = 0; i < n_in; i++) {
        switch (in_sizes[i]) {
            case 6291456: x  = (const float*)d_in[i]; break;   // [2,4096,768]
            case 1769472: Wa = (const float*)d_in[i]; break;   // [768,2304]
            case 2304:    ba = (const float*)d_in[i]; break;
            case 589824:  Wp = (const float*)d_in[i]; break;   // [768,768]
            case 768:     bp = (const float*)d_in[i]; break;
        }
    }

    cudaFuncSetAttribute(qkv_mma,   cudaFuncAttributeMaxDynamicSharedMemorySize, GSMEM4);
    cudaFuncSetAttribute(proj_mma,  cudaFuncAttributeMaxDynamicSharedMemorySize, GSMEM2);
    cudaFuncSetAttribute(flash_mma, cudaFuncAttributeMaxDynamicSharedMemorySize, FSMEM);

    __half *xd, *wat, *wpt;
    cudaGetSymbolAddress((void**)&xd,  g_x);
    cudaGetSymbolAddress((void**)&wat, g_WaT);
    cudaGetSymbolAddress((void**)&wpt, g_WpT);

    conv_f16<<<(MTOT*CDIM/2 + 255)/256, 256>>>(x, xd, MTOT*CDIM/2);
    wconv_T<<<dim3(N3DIM/32, CDIM/32), dim3(32, 8)>>>(Wa, wat, CDIM, N3DIM);
    wconv_T<<<dim3(CDIM/32,  CDIM/32), dim3(32, 8)>>>(Wp, wpt, CDIM, CDIM);
    qkv_mma<<<dim3(N3DIM/128, MTOT/256), 512, GSMEM4>>>(ba);       // (18,32)
    flash_mma<<<dim3(TDIM/128, BDIM*HDIM), 256, FSMEM>>>();        // (32,24)
    proj_mma<<<dim3(CDIM/128, MTOT/128), 512, GSMEM2>>>(bp, (float*)d_out); // (6,64)
}

// round 16
// speedup vs baseline: 1.0736x; 1.0343x over previous
#include <cuda_runtime.h>
#include <cuda_bf16.h>
#include <cuda_fp16.h>
#include <cstdint>

// ---------------------------------------------------------------------------
// Problem constants
// ---------------------------------------------------------------------------
#define BDIM 2
#define TDIM 4096
#define CDIM 768
#define HDIM 12
#define DDIM 64
#define N3DIM 2304            // 3*C
#define MTOT  (BDIM*TDIM)     // 8192

// ---------------------------------------------------------------------------
// Device scratch (no allocation in kernel_launch) — pure fp16 pipeline
// ---------------------------------------------------------------------------
__device__ __align__(16) __half g_x [MTOT*CDIM];
__device__ __align__(16) __half g_y [MTOT*CDIM];
__device__ __align__(16) __half g_WaT[N3DIM*CDIM];   // [N,K]
__device__ __align__(16) __half g_WpT[CDIM*CDIM];    // [N,K]
__device__ __align__(16) __half g_q[BDIM*HDIM*TDIM*DDIM];   // x0.125
__device__ __align__(16) __half g_k[BDIM*HDIM*TDIM*DDIM];
__device__ __align__(16) __half g_v[BDIM*HDIM*TDIM*DDIM];

// ---------------------------------------------------------------------------
// Helpers (all sm_80-legal: mma.sync fp16, ldmatrix, cp.async)
// ---------------------------------------------------------------------------
__device__ __forceinline__ uint32_t smem_u32(const void* p) {
    uint32_t a;
    asm("{ .reg .u64 t; cvta.to.shared.u64 t, %1; cvt.u32.u64 %0, t; }"
        : "=r"(a) : "l"(p));
    return a;
}
#define SW128(off) ((off) ^ (((off) >> 3) & 0x70))

__device__ __forceinline__ void cp16(uint32_t dst, const void* src) {
    asm volatile("cp.async.cg.shared.global [%0], [%1], 16;"
                 :: "r"(dst), "l"(src) : "memory");
}
#define CP_COMMIT() asm volatile("cp.async.commit_group;" ::: "memory")
#define CP_WAIT0()  asm volatile("cp.async.wait_group 0;"  ::: "memory")
#define CP_WAIT1()  asm volatile("cp.async.wait_group 1;"  ::: "memory")

__device__ __forceinline__ void ldm_x4(uint32_t a, uint32_t& r0, uint32_t& r1,
                                       uint32_t& r2, uint32_t& r3) {
    asm volatile("ldmatrix.sync.aligned.m8n8.x4.shared.b16 {%0,%1,%2,%3}, [%4];"
                 : "=r"(r0), "=r"(r1), "=r"(r2), "=r"(r3) : "r"(a));
}
__device__ __forceinline__ void ldm_x4t(uint32_t a, uint32_t& r0, uint32_t& r1,
                                        uint32_t& r2, uint32_t& r3) {
    asm volatile("ldmatrix.sync.aligned.m8n8.x4.trans.shared.b16 {%0,%1,%2,%3}, [%4];"
                 : "=r"(r0), "=r"(r1), "=r"(r2), "=r"(r3) : "r"(a));
}
__device__ __forceinline__ void mma_fp16(float (&c)[4], const uint32_t (&a)[4],
                                         uint32_t b0, uint32_t b1) {
    asm volatile("mma.sync.aligned.m16n8k16.row.col.f32.f16.f16.f32 "
                 "{%0,%1,%2,%3}, {%4,%5,%6,%7}, {%8,%9}, {%0,%1,%2,%3};"
                 : "+f"(c[0]), "+f"(c[1]), "+f"(c[2]), "+f"(c[3])
                 : "r"(a[0]), "r"(a[1]), "r"(a[2]), "r"(a[3]), "r"(b0), "r"(b1));
}
// pack two halves into u32 (a -> low, b -> high)
__device__ __forceinline__ uint32_t pkh(__half a, __half b) {
    __half2 t = __halves2half2(a, b);
    return *(uint32_t*)&t;
}
__device__ __forceinline__ float ex2f(float x) {
    float y; asm("ex2.approx.ftz.f32 %0, %1;" : "=f"(y) : "f"(x)); return y;
}

// ---------------------------------------------------------------------------
// Fused conversion kernel: ONE launch does
//   blocks [0, 3072):      x fp32 -> fp16 (8 elems/thread, uint4 store)
//   blocks [3072, 4800):   Wa [K,N] -> WaT [N,K] fp16 (32x32 tiles)
//   blocks [4800, 5376):   Wp [K,N] -> WpT [N,K] fp16
// ---------------------------------------------------------------------------
__device__ __forceinline__ void wtile_T(const float* __restrict__ W,
                                        __half* __restrict__ WT,
                                        int K, int N, int bn, int bk,
                                        int tid, float (*tile)[33]) {
    const int tx = tid & 31, ty = tid >> 5;        // (32, 8)
    #pragma unroll
    for (int i = 0; i < 4; i++)
        tile[ty + 8*i][tx] = W[(size_t)(bk + ty + 8*i) * N + bn + tx];
    __syncthreads();
    #pragma unroll
    for (int i = 0; i < 4; i++)
        WT[(size_t)(bn + ty + 8*i) * K + bk + tx] = __float2half_rn(tile[tx][ty + 8*i]);
}

__global__ __launch_bounds__(256) void fused_conv(const float* __restrict__ x,
                                                  const float* __restrict__ Wa,
                                                  const float* __restrict__ Wp,
                                                  __half* __restrict__ xd,
                                                  __half* __restrict__ wat,
                                                  __half* __restrict__ wpt) {
    __shared__ float tile[32][33];
    const int b = blockIdx.x, tid = threadIdx.x;
    if (b < 3072) {
        // x: 6291456 elems = 3072 blocks * 256 thr * 8
        size_t i = (((size_t)b << 8) + tid) << 3;
        float4 v0 = *(const float4*)(x + i);
        float4 v1 = *(const float4*)(x + i + 4);
        uint4 o;
        o.x = pkh(__float2half_rn(v0.x), __float2half_rn(v0.y));
        o.y = pkh(__float2half_rn(v0.z), __float2half_rn(v0.w));
        o.z = pkh(__float2half_rn(v1.x), __float2half_rn(v1.y));
        o.w = pkh(__float2half_rn(v1.z), __float2half_rn(v1.w));
        *(uint4*)(xd + i) = o;
    } else if (b < 4800) {
        // Wa: N3DIM/32 = 72 col-tiles, CDIM/32 = 24 row-tiles
        const int t = b - 3072;
        wtile_T(Wa, wat, CDIM, N3DIM, (t % 72) * 32, (t / 72) * 32, tid, tile);
    } else {
        // Wp: 24 x 24 tiles
        const int t = b - 4800;
        wtile_T(Wp, wpt, CDIM, CDIM, (t % 24) * 32, (t / 24) * 32, tid, tile);
    }
}

// ---------------------------------------------------------------------------
// Single-pass fp16 HMMA GEMM mainloop, templated warp-M (MF*16).
// 512 thr = 16 warps (4m x 4n), warp tile (MF*16)x32, CTA (MF*64)x128,
// K-chunk 64, 3-stage.  smem stage: A (MF*8KB) @0, B (16KB) @MF*8KB.
// ---------------------------------------------------------------------------
template<int MF>
__device__ __forceinline__ void gemm_issue(const __half* A, const __half* B,
                                           int am0, int bn0, int k0,
                                           uint32_t stbase, int tid) {
    #pragma unroll
    for (int i = 0; i < MF; i++) {                 // A: MF*64 rows
        int s2 = tid + (i << 9);
        int row = s2 >> 3, c16 = s2 & 7;
        cp16(stbase + SW128((uint32_t)(row*128 + (c16 << 4))),
             A + (size_t)(am0 + row) * 768 + k0 + (c16 << 3));
    }
    #pragma unroll
    for (int i = 0; i < 2; i++) {                  // B: 128 rows
        int s2 = tid + (i << 9);
        int row = s2 >> 3, c16 = s2 & 7;
        cp16(stbase + (uint32_t)(MF*8192) + SW128((uint32_t)(row*128 + (c16 << 4))),
             B + (size_t)(bn0 + row) * 768 + k0 + (c16 << 3));
    }
    CP_COMMIT();
}

template<int MF>
__device__ __forceinline__ void gemm_main(const __half* A, const __half* B,
                                          int am0, int bn0,
                                          float (&acc)[MF][4][4], char* sm) {
    const int GST = MF*8192 + 16384;
    const int tid = threadIdx.x;
    const int wid = tid >> 5, lane = tid & 31;
    const uint32_t sb = smem_u32(sm);
    const int wm0 = (wid & 3) * (MF*16);
    const int wn0 = (wid >> 2) * 32;
    const int r = lane & 7, g = lane >> 3;

    gemm_issue<MF>(A, B, am0, bn0, 0,  sb,       tid);
    gemm_issue<MF>(A, B, am0, bn0, 64, sb + GST, tid);

    for (int c = 0; c < 12; c++) {
        if (c < 11) CP_WAIT1(); else CP_WAIT0();
        __syncthreads();
        if (c < 10)
            gemm_issue<MF>(A, B, am0, bn0, (c+2)*64,
                           sb + (uint32_t)(((c+2)%3) * GST), tid);
        const uint32_t st = sb + (uint32_t)((c % 3) * GST);
        #pragma unroll
        for (int kf = 0; kf < 4; kf++) {
            const int k0 = kf * 16;
            uint32_t af[MF][4];
            #pragma unroll
            for (int mf = 0; mf < MF; mf++) {
                uint32_t off = SW128((uint32_t)(
                    (wm0 + mf*16 + ((g & 1) ? 8 : 0) + r) * 128 +
                    (k0 + ((g & 2) ? 8 : 0)) * 2));
                ldm_x4(st + off, af[mf][0], af[mf][1], af[mf][2], af[mf][3]);
            }
            uint32_t bf[4][2];
            #pragma unroll
            for (int nb = 0; nb < 2; nb++) {
                uint32_t off = SW128((uint32_t)(
                    (wn0 + nb*16 + ((g & 2) ? 8 : 0) + r) * 128 +
                    (k0 + ((g & 1) ? 8 : 0)) * 2));
                uint32_t t0, t1, t2, t3;
                ldm_x4(st + (uint32_t)(MF*8192) + off, t0, t1, t2, t3);
                bf[2*nb][0] = t0; bf[2*nb][1] = t1;
                bf[2*nb+1][0] = t2; bf[2*nb+1][1] = t3;
            }
            #pragma unroll
            for (int mf = 0; mf < MF; mf++)
                #pragma unroll
                for (int nf = 0; nf < 4; nf++)
                    mma_fp16(acc[mf][nf], af[mf], bf[nf][0], bf[nf][1]);
        }
    }
}

#define GSMEM4 (3*(4*8192 + 16384))   // qkv: 147456
#define GSMEM2 (3*(2*8192 + 16384))   // proj: 98304

// ---------------------------------------------------------------------------
// QKV GEMM: x @ W_attn + b.  q (x0.125), k, v -> fp16 [b*h][t][d].
// CTA 256x128, grid (18, 32), 512 threads
// ---------------------------------------------------------------------------
__global__ __launch_bounds__(512) void qkv_mma(const float* __restrict__ bias) {
    extern __shared__ char sm[];
    const int bm = blockIdx.y * 256;
    const int bn = blockIdx.x * 128;
    float acc[4][4][4] = {};
    gemm_main<4>(g_x, g_WaT, bm, bn, acc, sm);

    const int wid = threadIdx.x >> 5, lane = threadIdx.x & 31;
    const int which = bn / CDIM;              // 0=q 1=k 2=v (tiles never straddle)
    const int batch = bm >> 12;               // 256-row tile never straddles batch
    const float sc = (which == 0) ? 0.125f : 1.0f;
    __half* dst = which == 0 ? g_q : which == 1 ? g_k : g_v;

    #pragma unroll
    for (int nf = 0; nf < 4; nf++) {
        const int gcol = bn + (wid >> 2) * 32 + nf * 8 + (lane & 3) * 2;
        const float b0 = __ldg(bias + gcol), b1 = __ldg(bias + gcol + 1);
        const int within = gcol % CDIM;
        const int head = within >> 6, d = within & 63;
        #pragma unroll
        for (int mf = 0; mf < 4; mf++) {
            const int t = (bm & (TDIM - 1)) + (wid & 3) * 64 + mf * 16 + (lane >> 2);
            size_t o0 = ((size_t)(batch*HDIM + head)*TDIM + t)     * DDIM + d;
            size_t o1 = ((size_t)(batch*HDIM + head)*TDIM + t + 8) * DDIM + d;
            *(uint32_t*)(dst + o0) = pkh(__float2half_rn((acc[mf][nf][0]+b0)*sc),
                                         __float2half_rn((acc[mf][nf][1]+b1)*sc));
            *(uint32_t*)(dst + o1) = pkh(__float2half_rn((acc[mf][nf][2]+b0)*sc),
                                         __float2half_rn((acc[mf][nf][3]+b1)*sc));
        }
    }
}

// ---------------------------------------------------------------------------
// Projection GEMM: y @ W_proj + b -> d_out fp32.  CTA 128x128, grid (6, 64)
// ---------------------------------------------------------------------------
__global__ __launch_bounds__(512) void proj_mma(const float* __restrict__ bias,
                                                float* __restrict__ out) {
    extern __shared__ char sm[];
    const int bm = blockIdx.y * 128;
    const int bn = blockIdx.x * 128;
    float acc[2][4][4] = {};
    gemm_main<2>(g_y, g_WpT, bm, bn, acc, sm);

    const int wid = threadIdx.x >> 5, lane = threadIdx.x & 31;
    #pragma unroll
    for (int nf = 0; nf < 4; nf++) {
        const int gcol = bn + (wid >> 2) * 32 + nf * 8 + (lane & 3) * 2;
        const float b0 = __ldg(bias + gcol), b1 = __ldg(bias + gcol + 1);
        #pragma unroll
        for (int mf = 0; mf < 2; mf++) {
            const int m = bm + (wid & 3) * 32 + mf * 16 + (lane >> 2);
            *(float2*)(out + (size_t)m * CDIM + gcol) =
                make_float2(acc[mf][nf][0] + b0, acc[mf][nf][1] + b1);
            *(float2*)(out + (size_t)(m + 8) * CDIM + gcol) =
                make_float2(acc[mf][nf][2] + b0, acc[mf][nf][3] + b1);
        }
    }
}

// ---------------------------------------------------------------------------
// Flash attention (R13 form — the 342.6us best): pure fp16 single-pass HMMA,
// 128-wide K/V tiles, ping-pong S registers so S(jt+1) HMMAs execute under
// the softmax of tile jt.  grid (32 q-tiles, 24 bh), 256 thr, 1 CTA/SM.
// Q fp16 in registers; K,V in smem (stage 32KB: K@0 V@16K), 3-stage cp.async.
// ---------------------------------------------------------------------------
#define FSMEM (3*32768)

__global__ __launch_bounds__(256) void flash_mma() {
    extern __shared__ char sm[];
    const uint32_t sb = smem_u32(sm);
    const int tid = threadIdx.x, wid = tid >> 5, lane = tid & 31;
    const int qt = (int)gridDim.x - 1 - (int)blockIdx.x;   // heavy tiles first
    const int bh = blockIdx.y;
    const int qbase = qt * 128;
    const int ntiles = qt + 1;                              // 128-wide K tiles

    const __half* qp = g_q + (size_t)bh * TDIM * DDIM;
    const __half* kp = g_k + (size_t)bh * TDIM * DDIM;
    const __half* vp = g_v + (size_t)bh * TDIM * DDIM;

    // Q fragments, register resident
    uint32_t qf[4][4];
    {
        const int row = qbase + wid * 16 + (lane >> 2);
        const int colb = (lane & 3) * 2;
        #pragma unroll
        for (int kf = 0; kf < 4; kf++)
            #pragma unroll
            for (int a = 0; a < 4; a++) {
                int rr = row + ((a & 1) ? 8 : 0);
                int cc = kf * 16 + colb + ((a & 2) ? 8 : 0);
                qf[kf][a] = *(const uint32_t*)(qp + (size_t)rr * DDIM + cc);
            }
    }

    float m0 = -1e30f, m1 = -1e30f, l0 = 0.f, l1 = 0.f;
    float o[8][4] = {};
    const int r = lane & 7, g = lane >> 3;
    const float LOG2E = 1.4426950408889634f;

    // K/V tile loader (cp.async, 8 x 16B per thread; stage = 32KB)
    auto issue = [&](int jt) {
        const int kb = jt * 128;
        const uint32_t stg = sb + (uint32_t)((jt % 3) << 15);
        #pragma unroll
        for (int arr = 0; arr < 2; arr++) {
            const __half* base = arr == 0 ? kp : vp;
            #pragma unroll
            for (int i = 0; i < 4; i++) {
                int s2 = tid + (i << 8);            // 0..1023 (128 rows x 8)
                int row = s2 >> 3, c16 = s2 & 7;
                cp16(stg + (arr << 14) + SW128((uint32_t)(row*128 + (c16 << 4))),
                     base + (size_t)(kb + row) * DDIM + (c16 << 3));
            }
        }
        CP_COMMIT();
    };

    // S accumulation from K stage into the given register array
    auto computeS = [&](uint32_t st, float (&s)[16][4]) {
        #pragma unroll
        for (int nf = 0; nf < 16; nf++)
            #pragma unroll
            for (int q = 0; q < 4; q++) s[nf][q] = 0.f;
        #pragma unroll
        for (int kf = 0; kf < 4; kf++) {
            const int k0 = kf * 16;
            #pragma unroll
            for (int nb = 0; nb < 8; nb++) {
                uint32_t off = SW128((uint32_t)(
                    (nb*16 + ((g & 2) ? 8 : 0) + r) * 128 +
                    (k0 + ((g & 1) ? 8 : 0)) * 2));
                uint32_t h0, h1, h2, h3;
                ldm_x4(st + off, h0, h1, h2, h3);          // K
                mma_fp16(s[2*nb],   qf[kf], h0, h1);
                mma_fp16(s[2*nb+1], qf[kf], h2, h3);
            }
        }
    };

    float sA[16][4], sB[16][4];

    // Per-tile body: softmax+PV on scur while S(jt+1) accumulates into snx.
    auto body = [&](int jt, float (&scur)[16][4], float (&snx)[16][4]) {
        CP_WAIT0();              // tile jt+1 (if issued) fully arrived
        __syncthreads();         // visible CTA-wide; stage jt-1 free
        if (jt + 2 < ntiles) issue(jt + 2);
        const int kb = jt * 128;
        const uint32_t st = sb + (uint32_t)((jt % 3) << 15);

        // ---- S(jt+1) FIRST: fills the tensor pipe under the softmax below ----
        if (jt + 1 < ntiles)
            computeS(sb + (uint32_t)(((jt + 1) % 3) << 15), snx);

        // ---- causal mask (diagonal tile only) ----
        const int row0 = qbase + wid * 16 + (lane >> 2);
        if (kb + 127 > row0) {
            #pragma unroll
            for (int nf = 0; nf < 16; nf++) {
                int col = kb + nf * 8 + (lane & 3) * 2;
                if (col     > row0)     scur[nf][0] = -1e30f;
                if (col + 1 > row0)     scur[nf][1] = -1e30f;
                if (col     > row0 + 8) scur[nf][2] = -1e30f;
                if (col + 1 > row0 + 8) scur[nf][3] = -1e30f;
            }
        }

        // ---- online softmax ----
        float rmax0 = -1e30f, rmax1 = -1e30f;
        #pragma unroll
        for (int nf = 0; nf < 16; nf++) {
            rmax0 = fmaxf(rmax0, fmaxf(scur[nf][0], scur[nf][1]));
            rmax1 = fmaxf(rmax1, fmaxf(scur[nf][2], scur[nf][3]));
        }
        rmax0 = fmaxf(rmax0, __shfl_xor_sync(0xffffffffu, rmax0, 1));
        rmax0 = fmaxf(rmax0, __shfl_xor_sync(0xffffffffu, rmax0, 2));
        rmax1 = fmaxf(rmax1, __shfl_xor_sync(0xffffffffu, rmax1, 1));
        rmax1 = fmaxf(rmax1, __shfl_xor_sync(0xffffffffu, rmax1, 2));
        const float mn0 = fmaxf(m0, rmax0), mn1 = fmaxf(m1, rmax1);
        const float a0 = ex2f((m0 - mn0) * LOG2E);
        const float a1 = ex2f((m1 - mn1) * LOG2E);
        m0 = mn0; m1 = mn1;
        const float ml0 = mn0 * LOG2E, ml1 = mn1 * LOG2E;
        float rs0 = 0.f, rs1 = 0.f;
        #pragma unroll
        for (int nf = 0; nf < 16; nf++) {
            scur[nf][0] = ex2f(fmaf(scur[nf][0], LOG2E, -ml0));
            scur[nf][1] = ex2f(fmaf(scur[nf][1], LOG2E, -ml0));
            scur[nf][2] = ex2f(fmaf(scur[nf][2], LOG2E, -ml1));
            scur[nf][3] = ex2f(fmaf(scur[nf][3], LOG2E, -ml1));
            rs0 += scur[nf][0] + scur[nf][1];
            rs1 += scur[nf][2] + scur[nf][3];
        }
        rs0 += __shfl_xor_sync(0xffffffffu, rs0, 1);
        rs0 += __shfl_xor_sync(0xffffffffu, rs0, 2);
        rs1 += __shfl_xor_sync(0xffffffffu, rs1, 1);
        rs1 += __shfl_xor_sync(0xffffffffu, rs1, 2);
        l0 = l0 * a0 + rs0;
        l1 = l1 * a1 + rs1;
        #pragma unroll
        for (int nf = 0; nf < 8; nf++) {
            o[nf][0] *= a0; o[nf][1] *= a0;
            o[nf][2] *= a1; o[nf][3] *= a1;
        }

        // ---- P -> fp16 A-fragments ----
        uint32_t pf[8][4];
        #pragma unroll
        for (int j = 0; j < 8; j++) {
            #pragma unroll
            for (int half = 0; half < 2; half++) {
                pf[j][2*half]     = pkh(__float2half_rn(scur[2*j + half][0]),
                                        __float2half_rn(scur[2*j + half][1]));
                pf[j][2*half + 1] = pkh(__float2half_rn(scur[2*j + half][2]),
                                        __float2half_rn(scur[2*j + half][3]));
            }
        }

        // ---- O += P.V (tile jt), V^T via ldmatrix.trans ----
        #pragma unroll
        for (int j = 0; j < 8; j++) {
            #pragma unroll
            for (int nb = 0; nb < 4; nb++) {
                uint32_t off = SW128((uint32_t)(
                    (j*16 + ((g & 1) ? 8 : 0) + r) * 128 +
                    (nb*16 + ((g & 2) ? 8 : 0)) * 2));
                uint32_t h0, h1, h2, h3;
                ldm_x4t(st + 16384 + off, h0, h1, h2, h3);   // V
                mma_fp16(o[2*nb],   pf[j], h0, h1);
                mma_fp16(o[2*nb+1], pf[j], h2, h3);
            }
        }
    };

    // Prologue: load tiles 0 (and 1), compute S(0) into sA
    issue(0);
    if (ntiles > 1) { issue(1); CP_WAIT1(); } else { CP_WAIT0(); }
    __syncthreads();
    computeS(sb, sA);

    for (int jt = 0; jt < ntiles; jt++) {
        if (jt & 1) body(jt, sB, sA);
        else        body(jt, sA, sB);
    }

    // ---- epilogue: o / l -> fp16 into g_y ----
    const float inv0 = 1.0f / l0, inv1 = 1.0f / l1;
    const int batch = bh / HDIM, hh = bh % HDIM;
    const int row = qbase + wid * 16 + (lane >> 2);
    const size_t rb0 = ((size_t)(batch * TDIM + row))     * CDIM + hh * DDIM;
    const size_t rb1 = ((size_t)(batch * TDIM + row + 8)) * CDIM + hh * DDIM;
    #pragma unroll
    for (int nf = 0; nf < 8; nf++) {
        const int d = nf * 8 + (lane & 3) * 2;
        *(uint32_t*)(g_y + rb0 + d) = pkh(__float2half_rn(o[nf][0] * inv0),
                                          __float2half_rn(o[nf][1] * inv0));
        *(uint32_t*)(g_y + rb1 + d) = pkh(__float2half_rn(o[nf][2] * inv1),
                                          __float2half_rn(o[nf][3] * inv1));
    }
}

// ---------------------------------------------------------------------------
extern "C" void kernel_launch(void* const* d_in, const int* in_sizes, int n_in,
                              void* d_out, int out_size) {
    const float *x = nullptr, *Wa = nullptr, *ba = nullptr, *Wp = nullptr, *bp = nullptr;
    for (int i = 0; i < n_in; i++) {
        switch (in_sizes[i]) {
            case 6291456: x  = (const float*)d_in[i]; break;   // [2,4096,768]
            case 1769472: Wa = (const float*)d_in[i]; break;   // [768,2304]
            case 2304:    ba = (const float*)d_in[i]; break;
            case 589824:  Wp = (const float*)d_in[i]; break;   // [768,768]
            case 768:     bp = (const float*)d_in[i]; break;
        }
    }

    cudaFuncSetAttribute(qkv_mma,   cudaFuncAttributeMaxDynamicSharedMemorySize, GSMEM4);
    cudaFuncSetAttribute(proj_mma,  cudaFuncAttributeMaxDynamicSharedMemorySize, GSMEM2);
    cudaFuncSetAttribute(flash_mma, cudaFuncAttributeMaxDynamicSharedMemorySize, FSMEM);

    __half *xd, *wat, *wpt;
    cudaGetSymbolAddress((void**)&xd,  g_x);
    cudaGetSymbolAddress((void**)&wat, g_WaT);
    cudaGetSymbolAddress((void**)&wpt, g_WpT);

    fused_conv<<<5376, 256>>>(x, Wa, Wp, xd, wat, wpt);            // 1 launch
    qkv_mma<<<dim3(N3DIM/128, MTOT/256), 512, GSMEM4>>>(ba);       // (18,32)
    flash_mma<<<dim3(TDIM/128, BDIM*HDIM), 256, FSMEM>>>();        // (32,24)
    proj_mma<<<dim3(CDIM/128, MTOT/128), 512, GSMEM2>>>(bp, (float*)d_out); // (6,64)
}

// round 17
// speedup vs baseline: 1.1146x; 1.0382x over previous
#include <cuda_runtime.h>
#include <cuda_bf16.h>
#include <cuda_fp16.h>
#include <cstdint>

// ---------------------------------------------------------------------------
// Problem constants
// ---------------------------------------------------------------------------
#define BDIM 2
#define TDIM 4096
#define CDIM 768
#define HDIM 12
#define DDIM 64
#define N3DIM 2304            // 3*C
#define MTOT  (BDIM*TDIM)     // 8192

// ---------------------------------------------------------------------------
// Device scratch (no allocation in kernel_launch) — pure fp16 pipeline
// ---------------------------------------------------------------------------
__device__ __align__(16) __half g_x [MTOT*CDIM];
__device__ __align__(16) __half g_y [MTOT*CDIM];
__device__ __align__(16) __half g_WaT[N3DIM*CDIM];   // [N,K]
__device__ __align__(16) __half g_WpT[CDIM*CDIM];    // [N,K]
__device__ __align__(16) __half g_q[BDIM*HDIM*TDIM*DDIM];   // x0.125
__device__ __align__(16) __half g_k[BDIM*HDIM*TDIM*DDIM];
__device__ __align__(16) __half g_v[BDIM*HDIM*TDIM*DDIM];

// ---------------------------------------------------------------------------
// Helpers (all sm_80-legal: mma.sync fp16, ldmatrix, cp.async)
// ---------------------------------------------------------------------------
__device__ __forceinline__ uint32_t smem_u32(const void* p) {
    uint32_t a;
    asm("{ .reg .u64 t; cvta.to.shared.u64 t, %1; cvt.u32.u64 %0, t; }"
        : "=r"(a) : "l"(p));
    return a;
}
#define SW128(off) ((off) ^ (((off) >> 3) & 0x70))

__device__ __forceinline__ void cp16(uint32_t dst, const void* src) {
    asm volatile("cp.async.cg.shared.global [%0], [%1], 16;"
                 :: "r"(dst), "l"(src) : "memory");
}
#define CP_COMMIT() asm volatile("cp.async.commit_group;" ::: "memory")
#define CP_WAIT0()  asm volatile("cp.async.wait_group 0;"  ::: "memory")
#define CP_WAIT1()  asm volatile("cp.async.wait_group 1;"  ::: "memory")

__device__ __forceinline__ void ldm_x4(uint32_t a, uint32_t& r0, uint32_t& r1,
                                       uint32_t& r2, uint32_t& r3) {
    asm volatile("ldmatrix.sync.aligned.m8n8.x4.shared.b16 {%0,%1,%2,%3}, [%4];"
                 : "=r"(r0), "=r"(r1), "=r"(r2), "=r"(r3) : "r"(a));
}
__device__ __forceinline__ void ldm_x4t(uint32_t a, uint32_t& r0, uint32_t& r1,
                                        uint32_t& r2, uint32_t& r3) {
    asm volatile("ldmatrix.sync.aligned.m8n8.x4.trans.shared.b16 {%0,%1,%2,%3}, [%4];"
                 : "=r"(r0), "=r"(r1), "=r"(r2), "=r"(r3) : "r"(a));
}
__device__ __forceinline__ void mma_fp16(float (&c)[4], const uint32_t (&a)[4],
                                         uint32_t b0, uint32_t b1) {
    asm volatile("mma.sync.aligned.m16n8k16.row.col.f32.f16.f16.f32 "
                 "{%0,%1,%2,%3}, {%4,%5,%6,%7}, {%8,%9}, {%0,%1,%2,%3};"
                 : "+f"(c[0]), "+f"(c[1]), "+f"(c[2]), "+f"(c[3])
                 : "r"(a[0]), "r"(a[1]), "r"(a[2]), "r"(a[3]), "r"(b0), "r"(b1));
}
// pack two halves into u32 (a -> low, b -> high)
__device__ __forceinline__ uint32_t pkh(__half a, __half b) {
    __half2 t = __halves2half2(a, b);
    return *(uint32_t*)&t;
}
__device__ __forceinline__ float ex2f(float x) {
    float y; asm("ex2.approx.ftz.f32 %0, %1;" : "=f"(y) : "f"(x)); return y;
}

// ---------------------------------------------------------------------------
// Fused conversion kernel (unchanged from R16): ONE launch does
//   blocks [0, 3072):      x fp32 -> fp16 (8 elems/thread, uint4 store)
//   blocks [3072, 4800):   Wa [K,N] -> WaT [N,K] fp16 (32x32 tiles)
//   blocks [4800, 5376):   Wp [K,N] -> WpT [N,K] fp16
// ---------------------------------------------------------------------------
__device__ __forceinline__ void wtile_T(const float* __restrict__ W,
                                        __half* __restrict__ WT,
                                        int K, int N, int bn, int bk,
                                        int tid, float (*tile)[33]) {
    const int tx = tid & 31, ty = tid >> 5;        // (32, 8)
    #pragma unroll
    for (int i = 0; i < 4; i++)
        tile[ty + 8*i][tx] = W[(size_t)(bk + ty + 8*i) * N + bn + tx];
    __syncthreads();
    #pragma unroll
    for (int i = 0; i < 4; i++)
        WT[(size_t)(bn + ty + 8*i) * K + bk + tx] = __float2half_rn(tile[tx][ty + 8*i]);
}

__global__ __launch_bounds__(256) void fused_conv(const float* __restrict__ x,
                                                  const float* __restrict__ Wa,
                                                  const float* __restrict__ Wp,
                                                  __half* __restrict__ xd,
                                                  __half* __restrict__ wat,
                                                  __half* __restrict__ wpt) {
    __shared__ float tile[32][33];
    const int b = blockIdx.x, tid = threadIdx.x;
    if (b < 3072) {
        size_t i = (((size_t)b << 8) + tid) << 3;
        float4 v0 = *(const float4*)(x + i);
        float4 v1 = *(const float4*)(x + i + 4);
        uint4 o;
        o.x = pkh(__float2half_rn(v0.x), __float2half_rn(v0.y));
        o.y = pkh(__float2half_rn(v0.z), __float2half_rn(v0.w));
        o.z = pkh(__float2half_rn(v1.x), __float2half_rn(v1.y));
        o.w = pkh(__float2half_rn(v1.z), __float2half_rn(v1.w));
        *(uint4*)(xd + i) = o;
    } else if (b < 4800) {
        const int t = b - 3072;
        wtile_T(Wa, wat, CDIM, N3DIM, (t % 72) * 32, (t / 72) * 32, tid, tile);
    } else {
        const int t = b - 4800;
        wtile_T(Wp, wpt, CDIM, CDIM, (t % 24) * 32, (t / 24) * 32, tid, tile);
    }
}

// ---------------------------------------------------------------------------
// Single-pass fp16 HMMA GEMM mainloop, 256 thr = 8 warps (2m x 4n),
// warp tile 64x32, CTA tile 128x128, K-chunk 64, 3-stage (stage 32KB:
// A@0 16KB, B@16K 16KB).  96KB total -> 2 CTAs/SM.
// ---------------------------------------------------------------------------
__device__ __forceinline__ void gemm_issue(const __half* A, const __half* B,
                                           int am0, int bn0, int k0,
                                           uint32_t stbase, int tid) {
    #pragma unroll
    for (int i = 0; i < 4; i++) {                  // A: 128 rows
        int s2 = tid + (i << 8);
        int row = s2 >> 3, c16 = s2 & 7;
        cp16(stbase + SW128((uint32_t)(row*128 + (c16 << 4))),
             A + (size_t)(am0 + row) * 768 + k0 + (c16 << 3));
    }
    #pragma unroll
    for (int i = 0; i < 4; i++) {                  // B: 128 rows
        int s2 = tid + (i << 8);
        int row = s2 >> 3, c16 = s2 & 7;
        cp16(stbase + 16384u + SW128((uint32_t)(row*128 + (c16 << 4))),
             B + (size_t)(bn0 + row) * 768 + k0 + (c16 << 3));
    }
    CP_COMMIT();
}

__device__ __forceinline__ void gemm_main(const __half* A, const __half* B,
                                          int am0, int bn0,
                                          float (&acc)[4][4][4], char* sm) {
    const int GST = 32768;
    const int tid = threadIdx.x;
    const int wid = tid >> 5, lane = tid & 31;
    const uint32_t sb = smem_u32(sm);
    const int wm0 = (wid & 1) * 64;
    const int wn0 = (wid >> 1) * 32;
    const int r = lane & 7, g = lane >> 3;

    gemm_issue(A, B, am0, bn0, 0,  sb,       tid);
    gemm_issue(A, B, am0, bn0, 64, sb + GST, tid);

    for (int c = 0; c < 12; c++) {
        if (c < 11) CP_WAIT1(); else CP_WAIT0();
        __syncthreads();
        if (c < 10)
            gemm_issue(A, B, am0, bn0, (c+2)*64,
                       sb + (uint32_t)(((c+2)%3) * GST), tid);
        const uint32_t st = sb + (uint32_t)((c % 3) * GST);
        #pragma unroll
        for (int kf = 0; kf < 4; kf++) {
            const int k0 = kf * 16;
            uint32_t af[4][4];
            #pragma unroll
            for (int mf = 0; mf < 4; mf++) {
                uint32_t off = SW128((uint32_t)(
                    (wm0 + mf*16 + ((g & 1) ? 8 : 0) + r) * 128 +
                    (k0 + ((g & 2) ? 8 : 0)) * 2));
                ldm_x4(st + off, af[mf][0], af[mf][1], af[mf][2], af[mf][3]);
            }
            uint32_t bf[4][2];
            #pragma unroll
            for (int nb = 0; nb < 2; nb++) {
                uint32_t off = SW128((uint32_t)(
                    (wn0 + nb*16 + ((g & 2) ? 8 : 0) + r) * 128 +
                    (k0 + ((g & 1) ? 8 : 0)) * 2));
                uint32_t t0, t1, t2, t3;
                ldm_x4(st + 16384u + off, t0, t1, t2, t3);
                bf[2*nb][0] = t0; bf[2*nb][1] = t1;
                bf[2*nb+1][0] = t2; bf[2*nb+1][1] = t3;
            }
            #pragma unroll
            for (int mf = 0; mf < 4; mf++)
                #pragma unroll
                for (int nf = 0; nf < 4; nf++)
                    mma_fp16(acc[mf][nf], af[mf], bf[nf][0], bf[nf][1]);
        }
    }
}

#define GSMEM (3*32768)   // 98304, 2 CTAs/SM

// ---------------------------------------------------------------------------
// QKV GEMM: x @ W_attn + b.  q (x0.125), k, v -> fp16 [b*h][t][d].
// CTA 128x128, grid (18, 64), 256 threads, 2 CTAs/SM
// ---------------------------------------------------------------------------
__global__ void __launch_bounds__(256, 2) qkv_mma(const float* __restrict__ bias) {
    extern __shared__ char sm[];
    const int bm = blockIdx.y * 128;
    const int bn = blockIdx.x * 128;
    float acc[4][4][4] = {};
    gemm_main(g_x, g_WaT, bm, bn, acc, sm);

    const int wid = threadIdx.x >> 5, lane = threadIdx.x & 31;
    const int which = bn / CDIM;              // 0=q 1=k 2=v (tiles never straddle)
    const int batch = bm >> 12;               // 128-row tile never straddles batch
    const float sc = (which == 0) ? 0.125f : 1.0f;
    __half* dst = which == 0 ? g_q : which == 1 ? g_k : g_v;

    #pragma unroll
    for (int nf = 0; nf < 4; nf++) {
        const int gcol = bn + (wid >> 1) * 32 + nf * 8 + (lane & 3) * 2;
        const float b0 = __ldg(bias + gcol), b1 = __ldg(bias + gcol + 1);
        const int within = gcol % CDIM;
        const int head = within >> 6, d = within & 63;
        #pragma unroll
        for (int mf = 0; mf < 4; mf++) {
            const int t = (bm & (TDIM - 1)) + (wid & 1) * 64 + mf * 16 + (lane >> 2);
            size_t o0 = ((size_t)(batch*HDIM + head)*TDIM + t)     * DDIM + d;
            size_t o1 = ((size_t)(batch*HDIM + head)*TDIM + t + 8) * DDIM + d;
            *(uint32_t*)(dst + o0) = pkh(__float2half_rn((acc[mf][nf][0]+b0)*sc),
                                         __float2half_rn((acc[mf][nf][1]+b1)*sc));
            *(uint32_t*)(dst + o1) = pkh(__float2half_rn((acc[mf][nf][2]+b0)*sc),
                                         __float2half_rn((acc[mf][nf][3]+b1)*sc));
        }
    }
}

// ---------------------------------------------------------------------------
// Projection GEMM: y @ W_proj + b -> d_out fp32.  CTA 128x128, grid (6, 64),
// 256 threads, 2 CTAs/SM
// ---------------------------------------------------------------------------
__global__ void __launch_bounds__(256, 2) proj_mma(const float* __restrict__ bias,
                                                   float* __restrict__ out) {
    extern __shared__ char sm[];
    const int bm = blockIdx.y * 128;
    const int bn = blockIdx.x * 128;
    float acc[4][4][4] = {};
    gemm_main(g_y, g_WpT, bm, bn, acc, sm);

    const int wid = threadIdx.x >> 5, lane = threadIdx.x & 31;
    #pragma unroll
    for (int nf = 0; nf < 4; nf++) {
        const int gcol = bn + (wid >> 1) * 32 + nf * 8 + (lane & 3) * 2;
        const float b0 = __ldg(bias + gcol), b1 = __ldg(bias + gcol + 1);
        #pragma unroll
        for (int mf = 0; mf < 4; mf++) {
            const int m = bm + (wid & 1) * 64 + mf * 16 + (lane >> 2);
            *(float2*)(out + (size_t)m * CDIM + gcol) =
                make_float2(acc[mf][nf][0] + b0, acc[mf][nf][1] + b1);
            *(float2*)(out + (size_t)(m + 8) * CDIM + gcol) =
                make_float2(acc[mf][nf][2] + b0, acc[mf][nf][3] + b1);
        }
    }
}

// ---------------------------------------------------------------------------
// Flash attention (R13 form — unchanged): pure fp16 single-pass HMMA,
// 128-wide K/V tiles, ping-pong S registers so S(jt+1) HMMAs execute under
// the softmax of tile jt.  grid (32 q-tiles, 24 bh), 256 thr, 1 CTA/SM.
// Q fp16 in registers; K,V in smem (stage 32KB: K@0 V@16K), 3-stage cp.async.
// ---------------------------------------------------------------------------
#define FSMEM (3*32768)

__global__ __launch_bounds__(256) void flash_mma() {
    extern __shared__ char sm[];
    const uint32_t sb = smem_u32(sm);
    const int tid = threadIdx.x, wid = tid >> 5, lane = tid & 31;
    const int qt = (int)gridDim.x - 1 - (int)blockIdx.x;   // heavy tiles first
    const int bh = blockIdx.y;
    const int qbase = qt * 128;
    const int ntiles = qt + 1;                              // 128-wide K tiles

    const __half* qp = g_q + (size_t)bh * TDIM * DDIM;
    const __half* kp = g_k + (size_t)bh * TDIM * DDIM;
    const __half* vp = g_v + (size_t)bh * TDIM * DDIM;

    // Q fragments, register resident
    uint32_t qf[4][4];
    {
        const int row = qbase + wid * 16 + (lane >> 2);
        const int colb = (lane & 3) * 2;
        #pragma unroll
        for (int kf = 0; kf < 4; kf++)
            #pragma unroll
            for (int a = 0; a < 4; a++) {
                int rr = row + ((a & 1) ? 8 : 0);
                int cc = kf * 16 + colb + ((a & 2) ? 8 : 0);
                qf[kf][a] = *(const uint32_t*)(qp + (size_t)rr * DDIM + cc);
            }
    }

    float m0 = -1e30f, m1 = -1e30f, l0 = 0.f, l1 = 0.f;
    float o[8][4] = {};
    const int r = lane & 7, g = lane >> 3;
    const float LOG2E = 1.4426950408889634f;

    // K/V tile loader (cp.async, 8 x 16B per thread; stage = 32KB)
    auto issue = [&](int jt) {
        const int kb = jt * 128;
        const uint32_t stg = sb + (uint32_t)((jt % 3) << 15);
        #pragma unroll
        for (int arr = 0; arr < 2; arr++) {
            const __half* base = arr == 0 ? kp : vp;
            #pragma unroll
            for (int i = 0; i < 4; i++) {
                int s2 = tid + (i << 8);            // 0..1023 (128 rows x 8)
                int row = s2 >> 3, c16 = s2 & 7;
                cp16(stg + (arr << 14) + SW128((uint32_t)(row*128 + (c16 << 4))),
                     base + (size_t)(kb + row) * DDIM + (c16 << 3));
            }
        }
        CP_COMMIT();
    };

    // S accumulation from K stage into the given register array
    auto computeS = [&](uint32_t st, float (&s)[16][4]) {
        #pragma unroll
        for (int nf = 0; nf < 16; nf++)
            #pragma unroll
            for (int q = 0; q < 4; q++) s[nf][q] = 0.f;
        #pragma unroll
        for (int kf = 0; kf < 4; kf++) {
            const int k0 = kf * 16;
            #pragma unroll
            for (int nb = 0; nb < 8; nb++) {
                uint32_t off = SW128((uint32_t)(
                    (nb*16 + ((g & 2) ? 8 : 0) + r) * 128 +
                    (k0 + ((g & 1) ? 8 : 0)) * 2));
                uint32_t h0, h1, h2, h3;
                ldm_x4(st + off, h0, h1, h2, h3);          // K
                mma_fp16(s[2*nb],   qf[kf], h0, h1);
                mma_fp16(s[2*nb+1], qf[kf], h2, h3);
            }
        }
    };

    float sA[16][4], sB[16][4];

    // Per-tile body: softmax+PV on scur while S(jt+1) accumulates into snx.
    auto body = [&](int jt, float (&scur)[16][4], float (&snx)[16][4]) {
        CP_WAIT0();              // tile jt+1 (if issued) fully arrived
        __syncthreads();         // visible CTA-wide; stage jt-1 free
        if (jt + 2 < ntiles) issue(jt + 2);
        const int kb = jt * 128;
        const uint32_t st = sb + (uint32_t)((jt % 3) << 15);

        // ---- S(jt+1) FIRST: fills the tensor pipe under the softmax below ----
        if (jt + 1 < ntiles)
            computeS(sb + (uint32_t)(((jt + 1) % 3) << 15), snx);

        // ---- causal mask (diagonal tile only) ----
        const int row0 = qbase + wid * 16 + (lane >> 2);
        if (kb + 127 > row0) {
            #pragma unroll
            for (int nf = 0; nf < 16; nf++) {
                int col = kb + nf * 8 + (lane & 3) * 2;
                if (col     > row0)     scur[nf][0] = -1e30f;
                if (col + 1 > row0)     scur[nf][1] = -1e30f;
                if (col     > row0 + 8) scur[nf][2] = -1e30f;
                if (col + 1 > row0 + 8) scur[nf][3] = -1e30f;
            }
        }

        // ---- online softmax ----
        float rmax0 = -1e30f, rmax1 = -1e30f;
        #pragma unroll
        for (int nf = 0; nf < 16; nf++) {
            rmax0 = fmaxf(rmax0, fmaxf(scur[nf][0], scur[nf][1]));
            rmax1 = fmaxf(rmax1, fmaxf(scur[nf][2], scur[nf][3]));
        }
        rmax0 = fmaxf(rmax0, __shfl_xor_sync(0xffffffffu, rmax0, 1));
        rmax0 = fmaxf(rmax0, __shfl_xor_sync(0xffffffffu, rmax0, 2));
        rmax1 = fmaxf(rmax1, __shfl_xor_sync(0xffffffffu, rmax1, 1));
        rmax1 = fmaxf(rmax1, __shfl_xor_sync(0xffffffffu, rmax1, 2));
        const float mn0 = fmaxf(m0, rmax0), mn1 = fmaxf(m1, rmax1);
        const float a0 = ex2f((m0 - mn0) * LOG2E);
        const float a1 = ex2f((m1 - mn1) * LOG2E);
        m0 = mn0; m1 = mn1;
        const float ml0 = mn0 * LOG2E, ml1 = mn1 * LOG2E;
        float rs0 = 0.f, rs1 = 0.f;
        #pragma unroll
        for (int nf = 0; nf < 16; nf++) {
            scur[nf][0] = ex2f(fmaf(scur[nf][0], LOG2E, -ml0));
            scur[nf][1] = ex2f(fmaf(scur[nf][1], LOG2E, -ml0));
            scur[nf][2] = ex2f(fmaf(scur[nf][2], LOG2E, -ml1));
            scur[nf][3] = ex2f(fmaf(scur[nf][3], LOG2E, -ml1));
            rs0 += scur[nf][0] + scur[nf][1];
            rs1 += scur[nf][2] + scur[nf][3];
        }
        rs0 += __shfl_xor_sync(0xffffffffu, rs0, 1);
        rs0 += __shfl_xor_sync(0xffffffffu, rs0, 2);
        rs1 += __shfl_xor_sync(0xffffffffu, rs1, 1);
        rs1 += __shfl_xor_sync(0xffffffffu, rs1, 2);
        l0 = l0 * a0 + rs0;
        l1 = l1 * a1 + rs1;
        #pragma unroll
        for (int nf = 0; nf < 8; nf++) {
            o[nf][0] *= a0; o[nf][1] *= a0;
            o[nf][2] *= a1; o[nf][3] *= a1;
        }

        // ---- P -> fp16 A-fragments ----
        uint32_t pf[8][4];
        #pragma unroll
        for (int j = 0; j < 8; j++) {
            #pragma unroll
            for (int half = 0; half < 2; half++) {
                pf[j][2*half]     = pkh(__float2half_rn(scur[2*j + half][0]),
                                        __float2half_rn(scur[2*j + half][1]));
                pf[j][2*half + 1] = pkh(__float2half_rn(scur[2*j + half][2]),
                                        __float2half_rn(scur[2*j + half][3]));
            }
        }

        // ---- O += P.V (tile jt), V^T via ldmatrix.trans ----
        #pragma unroll
        for (int j = 0; j < 8; j++) {
            #pragma unroll
            for (int nb = 0; nb < 4; nb++) {
                uint32_t off = SW128((uint32_t)(
                    (j*16 + ((g & 1) ? 8 : 0) + r) * 128 +
                    (nb*16 + ((g & 2) ? 8 : 0)) * 2));
                uint32_t h0, h1, h2, h3;
                ldm_x4t(st + 16384 + off, h0, h1, h2, h3);   // V
                mma_fp16(o[2*nb],   pf[j], h0, h1);
                mma_fp16(o[2*nb+1], pf[j], h2, h3);
            }
        }
    };

    // Prologue: load tiles 0 (and 1), compute S(0) into sA
    issue(0);
    if (ntiles > 1) { issue(1); CP_WAIT1(); } else { CP_WAIT0(); }
    __syncthreads();
    computeS(sb, sA);

    for (int jt = 0; jt < ntiles; jt++) {
        if (jt & 1) body(jt, sB, sA);
        else        body(jt, sA, sB);
    }

    // ---- epilogue: o / l -> fp16 into g_y ----
    const float inv0 = 1.0f / l0, inv1 = 1.0f / l1;
    const int batch = bh / HDIM, hh = bh % HDIM;
    const int row = qbase + wid * 16 + (lane >> 2);
    const size_t rb0 = ((size_t)(batch * TDIM + row))     * CDIM + hh * DDIM;
    const size_t rb1 = ((size_t)(batch * TDIM + row + 8)) * CDIM + hh * DDIM;
    #pragma unroll
    for (int nf = 0; nf < 8; nf++) {
        const int d = nf * 8 + (lane & 3) * 2;
        *(uint32_t*)(g_y + rb0 + d) = pkh(__float2half_rn(o[nf][0] * inv0),
                                          __float2half_rn(o[nf][1] * inv0));
        *(uint32_t*)(g_y + rb1 + d) = pkh(__float2half_rn(o[nf][2] * inv1),
                                          __float2half_rn(o[nf][3] * inv1));
    }
}

// ---------------------------------------------------------------------------
extern "C" void kernel_launch(void* const* d_in, const int* in_sizes, int n_in,
                              void* d_out, int out_size) {
    const float *x = nullptr, *Wa = nullptr, *ba = nullptr, *Wp = nullptr, *bp = nullptr;
    for (int i = 0; i < n_in; i++) {
        switch (in_sizes[i]) {
            case 6291456: x  = (const float*)d_in[i]; break;   // [2,4096,768]
            case 1769472: Wa = (const float*)d_in[i]; break;   // [768,2304]
            case 2304:    ba = (const float*)d_in[i]; break;
            case 589824:  Wp = (const float*)d_in[i]; break;   // [768,768]
            case 768:     bp = (const float*)d_in[i]; break;
        }
    }

    cudaFuncSetAttribute(qkv_mma,   cudaFuncAttributeMaxDynamicSharedMemorySize, GSMEM);
    cudaFuncSetAttribute(proj_mma,  cudaFuncAttributeMaxDynamicSharedMemorySize, GSMEM);
    cudaFuncSetAttribute(flash_mma, cudaFuncAttributeMaxDynamicSharedMemorySize, FSMEM);

    __half *xd, *wat, *wpt;
    cudaGetSymbolAddress((void**)&xd,  g_x);
    cudaGetSymbolAddress((void**)&wat, g_WaT);
    cudaGetSymbolAddress((void**)&wpt, g_WpT);

    fused_conv<<<5376, 256>>>(x, Wa, Wp, xd, wat, wpt);            // 1 launch
    qkv_mma<<<dim3(N3DIM/128, MTOT/128), 256, GSMEM>>>(ba);        // (18,64)
    flash_mma<<<dim3(TDIM/128, BDIM*HDIM), 256, FSMEM>>>();        // (32,24)
    proj_mma<<<dim3(CDIM/128, MTOT/128), 256, GSMEM>>>(bp, (float*)d_out); // (6,64)
}